// round 10
// baseline (speedup 1.0000x reference)
#include <cuda_runtime.h>
#include <cuda_fp16.h>
#include <stdint.h>

#define NN 4096
#define FC 256      // F_IN == F_OUT
#define BB 8
#define WORDS (NN / 32)
#define NPAIR 4     // 4 chunks of 2 batches

// ---------------- scratch (no allocations allowed) ----------------
__device__ uint32_t g_adj[NN * WORDS];            // 2 MB bitmask adjacency
__device__ __half   g_xt[(size_t)BB * NN * FC];   // 16 MB: xt = x @ W (fp16)
__device__ __half   g_xh[(size_t)BB * NN * FC];   // 16 MB: x as fp16
__device__ __half   g_wh[FC * FC];                // 128 KB: W^T as fp16 [n][k]

// =================== streams/events (static init; serial fallback) ===========
__global__ void k_noop() {}

static cudaStream_t g_s1 = 0, g_s2 = 0;
static cudaEvent_t  g_evFork = 0, g_evG[NPAIR] = {0, 0, 0, 0}, g_evJ = 0;
static bool g_ok = false;

namespace {
struct SInit {
    SInit() {
        bool ok = true;
        ok &= cudaStreamCreateWithFlags(&g_s1, cudaStreamNonBlocking) == cudaSuccess;
        ok &= cudaStreamCreateWithFlags(&g_s2, cudaStreamNonBlocking) == cudaSuccess;
        ok &= cudaEventCreateWithFlags(&g_evFork, cudaEventDisableTiming) == cudaSuccess;
        for (int i = 0; i < NPAIR; i++)
            ok &= cudaEventCreateWithFlags(&g_evG[i], cudaEventDisableTiming) == cudaSuccess;
        ok &= cudaEventCreateWithFlags(&g_evJ, cudaEventDisableTiming) == cudaSuccess;
        if (ok) {   // warm streams so lazy driver work happens pre-checkpoint
            k_noop<<<1, 32, 0, g_s1>>>();
            k_noop<<<1, 32, 0, g_s2>>>();
            ok &= cudaDeviceSynchronize() == cudaSuccess;
        }
        g_ok = ok;
    }
};
SInit g_sinit;
}

// =================== setup kernels ===================
__global__ void k_clear_adj() {
    int i = blockIdx.x * blockDim.x + threadIdx.x;
    if (i < NN * WORDS) g_adj[i] = 0u;
}
__global__ void k_scatter(const int* __restrict__ ei, int E) {
    int e = blockIdx.x * blockDim.x + threadIdx.x;
    if (e < E) {
        int src = ei[e];
        int dst = ei[E + e];
        atomicOr(&g_adj[src * WORDS + (dst >> 5)], 1u << (dst & 31));
    }
}
// W[k][n] -> g_wh[n][k] fp16 (tiled transpose, coalesced)
__global__ void k_wt(const float* __restrict__ W) {
    __shared__ float tile[32][33];
    const int bn = blockIdx.x * 32;
    const int bk = blockIdx.y * 32;
    const int tx = threadIdx.x, ty = threadIdx.y;
#pragma unroll
    for (int r = ty; r < 32; r += 8)
        tile[r][tx] = W[(size_t)(bk + r) * FC + bn + tx];
    __syncthreads();
#pragma unroll
    for (int r = ty; r < 32; r += 8)
        g_wh[(size_t)(bn + r) * FC + bk + tx] = __float2half_rn(tile[tx][r]);
}
// x (fp32) -> g_xh (fp16), streaming; one 2-batch slice per launch
__global__ __launch_bounds__(256) void k_cvt(const float* __restrict__ x, int b0) {
    const size_t base = (size_t)b0 * NN * FC;
    const size_t i = base + ((size_t)blockIdx.x * 256 + threadIdx.x) * 8;
    float4 v0 = *(const float4*)&x[i];
    float4 v1 = *(const float4*)&x[i + 4];
    __half2 h0 = __floats2half2_rn(v0.x, v0.y);
    __half2 h1 = __floats2half2_rn(v0.z, v0.w);
    __half2 h2 = __floats2half2_rn(v1.x, v1.y);
    __half2 h3 = __floats2half2_rn(v1.z, v1.w);
    *(uint4*)&g_xh[i] = make_uint4(*(uint32_t*)&h0, *(uint32_t*)&h1,
                                   *(uint32_t*)&h2, *(uint32_t*)&h3);
}

// =================== mma / cp.async / ldmatrix helpers ===================
__device__ __forceinline__ void mma_f16(float* d, const uint32_t* a, const uint32_t* b) {
    asm volatile(
        "mma.sync.aligned.m16n8k16.row.col.f32.f16.f16.f32 "
        "{%0,%1,%2,%3}, {%4,%5,%6,%7}, {%8,%9}, {%0,%1,%2,%3};"
        : "+f"(d[0]), "+f"(d[1]), "+f"(d[2]), "+f"(d[3])
        : "r"(a[0]), "r"(a[1]), "r"(a[2]), "r"(a[3]),
          "r"(b[0]), "r"(b[1]));
}
__device__ __forceinline__ uint32_t smem_u32(const void* p) {
    uint32_t a;
    asm("{ .reg .u64 t; cvta.to.shared.u64 t, %1; cvt.u32.u64 %0, t; }" : "=r"(a) : "l"(p));
    return a;
}
#define LDSM_X4(r0, r1, r2, r3, addr)                                        \
    asm volatile("ldmatrix.sync.aligned.m8n8.x4.shared.b16 {%0,%1,%2,%3}, [%4];" \
        : "=r"(r0), "=r"(r1), "=r"(r2), "=r"(r3) : "r"(addr))
#define CP_ASYNC16(dst, src) \
    asm volatile("cp.async.cg.shared.global [%0], [%1], 16;" :: "r"(dst), "l"(src))
#define CP_COMMIT() asm volatile("cp.async.commit_group;" ::: "memory")
#define CP_WAIT0()  asm volatile("cp.async.wait_group 0;" ::: "memory")
#define CP_WAIT1()  asm volatile("cp.async.wait_group 1;" ::: "memory")

// =================== kernel: xt = xh @ Wh  (R7 fp16 mma + ldmatrix, BK=64) ===
#define BM 128
#define BN 128
#define BK 64
#define NCH (FC / BK)            // 4
#define TILE_B  (128 * 128)      // 16 KB per (A or B) tile
#define STAGE_B (2 * TILE_B)     // 32 KB
#define A_OFF(p) ((p) * STAGE_B)
#define B_OFF(p) ((p) * STAGE_B + TILE_B)
#define GEMM_SMEM (2 * STAGE_B)  // 64 KB

__global__ __launch_bounds__(256, 2) void k_gemm(int row_base) {
    extern __shared__ char sm[];
    const uint32_t sb = smem_u32(sm);

    const int tid  = threadIdx.x;
    const int lane = tid & 31;
    const int wid  = tid >> 5;
    const int wm = (wid & 1) * 64;
    const int wn = (wid >> 1) * 32;
    const int bm = row_base + blockIdx.x * BM;
    const int bn = blockIdx.y * BN;
    const int g  = lane >> 2;
    const int tg = lane & 3;

    const int cp_row = tid >> 3;
    const int cp_c   = tid & 7;

    const int a_lrow  = lane & 15;
    const int a_lchnk = lane >> 4;
    const int b_lrow  = ((lane >> 4) << 3) + (lane & 7);
    const int b_lchnk = (lane >> 3) & 1;

    float acc[4][4][4];
#pragma unroll
    for (int mt = 0; mt < 4; mt++)
#pragma unroll
        for (int nt = 0; nt < 4; nt++)
#pragma unroll
            for (int r = 0; r < 4; r++) acc[mt][nt][r] = 0.0f;

    auto issue = [&](int c, int p) {
        const int k0 = c * BK;
#pragma unroll
        for (int q = 0; q < 4; q++) {          // A: 128 rows x 64 halves
            int row = q * 32 + cp_row;
            uint32_t dst = sb + A_OFF(p) + row * 128 + ((cp_c ^ (row & 7)) << 4);
            CP_ASYNC16(dst, &g_xh[(size_t)(bm + row) * FC + k0 + cp_c * 8]);
        }
#pragma unroll
        for (int q = 0; q < 4; q++) {          // B: 128 rows x 64 halves
            int row = q * 32 + cp_row;
            uint32_t dst = sb + B_OFF(p) + row * 128 + ((cp_c ^ (row & 7)) << 4);
            CP_ASYNC16(dst, &g_wh[(size_t)(bn + row) * FC + k0 + cp_c * 8]);
        }
        CP_COMMIT();
    };

    issue(0, 0);
    issue(1, 1);

#pragma unroll
    for (int c = 0; c < NCH; c++) {
        const int p = c & 1;
        if (c == NCH - 1) { CP_WAIT0(); } else { CP_WAIT1(); }
        __syncthreads();

        const uint32_t sA = sb + A_OFF(p);
        const uint32_t sB = sb + B_OFF(p);

#pragma unroll
        for (int s = 0; s < 4; s++) {
            uint32_t a[4][4], b[4][2];
#pragma unroll
            for (int mt = 0; mt < 4; mt++) {
                int row = wm + mt * 16 + a_lrow;
                int ch  = (s * 2 + a_lchnk) ^ (row & 7);
                LDSM_X4(a[mt][0], a[mt][1], a[mt][2], a[mt][3],
                        sA + row * 128 + (ch << 4));
            }
#pragma unroll
            for (int pr = 0; pr < 2; pr++) {
                int row = wn + pr * 16 + b_lrow;
                int ch  = (s * 2 + b_lchnk) ^ (row & 7);
                LDSM_X4(b[pr * 2][0], b[pr * 2][1], b[pr * 2 + 1][0], b[pr * 2 + 1][1],
                        sB + row * 128 + (ch << 4));
            }
#pragma unroll
            for (int mt = 0; mt < 4; mt++)
#pragma unroll
                for (int nt = 0; nt < 4; nt++)
                    mma_f16(acc[mt][nt], a[mt], b[nt]);
        }
        __syncthreads();
        if (c + 2 < NCH) issue(c + 2, p);
    }

#pragma unroll
    for (int mt = 0; mt < 4; mt++) {
#pragma unroll
        for (int nt = 0; nt < 4; nt++) {
            int r = bm + wm + mt * 16 + g;
            int c = bn + wn + nt * 8 + tg * 2;
            __half2 h01 = __floats2half2_rn(acc[mt][nt][0], acc[mt][nt][1]);
            __half2 h23 = __floats2half2_rn(acc[mt][nt][2], acc[mt][nt][3]);
            *(__half2*)&g_xt[(size_t)r * FC + c]       = h01;
            *(__half2*)&g_xt[(size_t)(r + 8) * FC + c] = h23;
        }
    }
}

// =================== kernel: aggregate, 2 batches per launch ===================
// block = node i, 64 threads: batch b0+(t>>5), features (t&31)*8 (LDG.128/nbr)
__global__ __launch_bounds__(64) void k_aggregate2(const float* __restrict__ bias,
                                                   float* __restrict__ out, int b0) {
    __shared__ int      s_nbr[NN];
    __shared__ uint32_t s_words[WORDS];
    __shared__ int      s_off[WORDS];
    __shared__ int      s_total;

    const int i = blockIdx.x;
    const int t = threadIdx.x;

    {   // load 128 adjacency words (8B/thread, coalesced)
        uint2 w2 = *(const uint2*)&g_adj[i * WORDS + 2 * t];
        s_words[2 * t]     = w2.x;
        s_words[2 * t + 1] = w2.y;
    }
    __syncthreads();

    if (t < 32) {   // warp 0: exclusive scan of 128 popcounts (4/lane)
        int v0 = __popc(s_words[4 * t]);
        int v1 = __popc(s_words[4 * t + 1]);
        int v2 = __popc(s_words[4 * t + 2]);
        int v3 = __popc(s_words[4 * t + 3]);
        int sum = v0 + v1 + v2 + v3;
        int inc = sum;
#pragma unroll
        for (int d = 1; d < 32; d <<= 1) {
            int x = __shfl_up_sync(0xFFFFFFFFu, inc, d);
            if (t >= d) inc += x;
        }
        int exc = inc - sum;
        s_off[4 * t]     = exc;
        s_off[4 * t + 1] = exc + v0;
        s_off[4 * t + 2] = exc + v0 + v1;
        s_off[4 * t + 3] = exc + v0 + v1 + v2;
        if (t == 31) s_total = inc;
    }
    __syncthreads();

    {   // expand 2 words per thread (deterministic placement)
#pragma unroll
        for (int h = 0; h < 2; h++) {
            int wdx = 2 * t + h;
            int pos = s_off[wdx];
            uint32_t m = s_words[wdx];
            while (m) {
                int bit = __ffs(m) - 1;
                m &= m - 1;
                s_nbr[pos++] = wdx * 32 + bit;
            }
        }
    }
    __syncthreads();

    const int n = s_total;
    const float inv = 1.0f / ((float)n + 1e-6f);
    const int b  = b0 + (t >> 5);
    const int f8 = (t & 31) * 8;
    const __half* __restrict__ xb = g_xt + (size_t)b * NN * FC + f8;

    float a0 = 0.f, a1 = 0.f, a2 = 0.f, a3 = 0.f;
    float a4 = 0.f, a5 = 0.f, a6 = 0.f, a7 = 0.f;

#define ACC8(v)                                               \
    do { const __half2* _h = (const __half2*)&(v); float2 _p; \
        _p = __half22float2(_h[0]); a0 += _p.x; a1 += _p.y;   \
        _p = __half22float2(_h[1]); a2 += _p.x; a3 += _p.y;   \
        _p = __half22float2(_h[2]); a4 += _p.x; a5 += _p.y;   \
        _p = __half22float2(_h[3]); a6 += _p.x; a7 += _p.y; } while (0)

    int k = 0;
    for (; k + 4 <= n; k += 4) {
        uint4 v0 = *(const uint4*)&xb[(size_t)s_nbr[k]     * FC];
        uint4 v1 = *(const uint4*)&xb[(size_t)s_nbr[k + 1] * FC];
        uint4 v2 = *(const uint4*)&xb[(size_t)s_nbr[k + 2] * FC];
        uint4 v3 = *(const uint4*)&xb[(size_t)s_nbr[k + 3] * FC];
        ACC8(v0); ACC8(v1); ACC8(v2); ACC8(v3);
    }
    for (; k < n; k++) {
        uint4 v0 = *(const uint4*)&xb[(size_t)s_nbr[k] * FC];
        ACC8(v0);
    }
#undef ACC8

    float4 bl = *(const float4*)&bias[f8];
    float4 bh = *(const float4*)&bias[f8 + 4];
    float* o = out + ((size_t)b * NN + i) * FC + f8;
    *(float4*)o       = make_float4(a0 * inv + bl.x, a1 * inv + bl.y,
                                    a2 * inv + bl.z, a3 * inv + bl.w);
    *(float4*)(o + 4) = make_float4(a4 * inv + bh.x, a5 * inv + bh.y,
                                    a6 * inv + bh.z, a7 * inv + bh.w);
}

// =================== launch ===================
extern "C" void kernel_launch(void* const* d_in, const int* in_sizes, int n_in,
                              void* d_out, int out_size) {
    const float* x    = (const float*)d_in[0];
    const int*   ei   = (const int*)d_in[1];
    const float* w    = (const float*)d_in[2];
    const float* bias = (const float*)d_in[3];
    float*       out  = (float*)d_out;

    const int E = in_sizes[1] / 2;
    const int CVT_BLKS = 2 * NN * FC / (256 * 8);   // 1024 per 2-batch slice

    cudaFuncSetAttribute(k_gemm, cudaFuncAttributeMaxDynamicSharedMemorySize,
                         GEMM_SMEM);

    // setup on the capture (legacy) stream
    k_clear_adj<<<(NN * WORDS + 255) / 256, 256, 0, 0>>>();
    k_scatter<<<(E + 255) / 256, 256, 0, 0>>>(ei, E);
    {
        dim3 tb(32, 8);
        dim3 tg(FC / 32, FC / 32);
        k_wt<<<tg, tb, 0, 0>>>(w);
    }

    dim3 ggrid(2 * NN / BM, FC / BN);   // 64 x 2 CTAs per 2-batch chunk

    if (g_ok) {
        // fork: s1 = cvt+gemm chain, s2 = aggregate chain
        cudaEventRecord(g_evFork, 0);
        cudaStreamWaitEvent(g_s1, g_evFork, 0);
        for (int c = 0; c < NPAIR; c++) {
            const int b0 = 2 * c;
            k_cvt<<<CVT_BLKS, 256, 0, g_s1>>>(x, b0);
            k_gemm<<<ggrid, 256, GEMM_SMEM, g_s1>>>(b0 * NN);
            cudaEventRecord(g_evG[c], g_s1);
            cudaStreamWaitEvent(g_s2, g_evG[c], 0);
            k_aggregate2<<<NN, 64, 0, g_s2>>>(bias, out, b0);
        }
        // join both streams back to the capture stream
        cudaEventRecord(g_evJ, g_s2);
        cudaStreamWaitEvent(0, g_evG[NPAIR - 1], 0);
        cudaStreamWaitEvent(0, g_evJ, 0);
    } else {
        // serial fallback: identical math on one stream
        for (int c = 0; c < NPAIR; c++) {
            const int b0 = 2 * c;
            k_cvt<<<CVT_BLKS, 256, 0, 0>>>(x, b0);
            k_gemm<<<ggrid, 256, GEMM_SMEM, 0>>>(b0 * NN);
            k_aggregate2<<<NN, 64, 0, 0>>>(bias, out, b0);
        }
    }
}

// round 11
// speedup vs baseline: 1.1940x; 1.1940x over previous
#include <cuda_runtime.h>
#include <cuda_fp16.h>
#include <stdint.h>

#define NN 4096
#define FC 256      // F_IN == F_OUT
#define BB 8
#define WORDS (NN / 32)
#define NHALF 2     // 2 chunks of 4 batches

// ---------------- scratch (no allocations allowed) ----------------
__device__ uint32_t g_adj[NN * WORDS];            // 2 MB bitmask adjacency
__device__ __half   g_xt[(size_t)BB * NN * FC];   // 16 MB: xt = x @ W (fp16)
__device__ __half   g_xh[(size_t)BB * NN * FC];   // 16 MB: x as fp16
__device__ __half   g_wh[FC * FC];                // 128 KB: W^T as fp16 [n][k]

// =================== streams/events (static init; serial fallback) ===========
__global__ void k_noop() {}

static cudaStream_t g_s1 = 0, g_s2 = 0;
static cudaEvent_t  g_evFork = 0, g_evG[NHALF] = {0, 0}, g_evJ = 0;
static bool g_ok = false;

namespace {
struct SInit {
    SInit() {
        bool ok = true;
        ok &= cudaStreamCreateWithFlags(&g_s1, cudaStreamNonBlocking) == cudaSuccess;
        ok &= cudaStreamCreateWithFlags(&g_s2, cudaStreamNonBlocking) == cudaSuccess;
        ok &= cudaEventCreateWithFlags(&g_evFork, cudaEventDisableTiming) == cudaSuccess;
        for (int i = 0; i < NHALF; i++)
            ok &= cudaEventCreateWithFlags(&g_evG[i], cudaEventDisableTiming) == cudaSuccess;
        ok &= cudaEventCreateWithFlags(&g_evJ, cudaEventDisableTiming) == cudaSuccess;
        if (ok) {
            k_noop<<<1, 32, 0, g_s1>>>();
            k_noop<<<1, 32, 0, g_s2>>>();
            ok &= cudaDeviceSynchronize() == cudaSuccess;
        }
        g_ok = ok;
    }
};
SInit g_sinit;
}

// =================== setup kernels ===================
__global__ void k_clear_adj() {
    int i = blockIdx.x * blockDim.x + threadIdx.x;
    if (i < NN * WORDS) g_adj[i] = 0u;
}
__global__ void k_scatter(const int* __restrict__ ei, int E) {
    int e = blockIdx.x * blockDim.x + threadIdx.x;
    if (e < E) {
        int src = ei[e];
        int dst = ei[E + e];
        atomicOr(&g_adj[src * WORDS + (dst >> 5)], 1u << (dst & 31));
    }
}
// W[k][n] -> g_wh[n][k] fp16 (tiled transpose, coalesced)
__global__ void k_wt(const float* __restrict__ W) {
    __shared__ float tile[32][33];
    const int bn = blockIdx.x * 32;
    const int bk = blockIdx.y * 32;
    const int tx = threadIdx.x, ty = threadIdx.y;
#pragma unroll
    for (int r = ty; r < 32; r += 8)
        tile[r][tx] = W[(size_t)(bk + r) * FC + bn + tx];
    __syncthreads();
#pragma unroll
    for (int r = ty; r < 32; r += 8)
        g_wh[(size_t)(bn + r) * FC + bk + tx] = __float2half_rn(tile[tx][r]);
}
// x (fp32) -> g_xh (fp16), streaming; one 4-batch slice per launch
__global__ __launch_bounds__(256) void k_cvt(const float* __restrict__ x, int b0) {
    const size_t base = (size_t)b0 * NN * FC;
    const size_t i = base + ((size_t)blockIdx.x * 256 + threadIdx.x) * 8;
    float4 v0 = *(const float4*)&x[i];
    float4 v1 = *(const float4*)&x[i + 4];
    __half2 h0 = __floats2half2_rn(v0.x, v0.y);
    __half2 h1 = __floats2half2_rn(v0.z, v0.w);
    __half2 h2 = __floats2half2_rn(v1.x, v1.y);
    __half2 h3 = __floats2half2_rn(v1.z, v1.w);
    *(uint4*)&g_xh[i] = make_uint4(*(uint32_t*)&h0, *(uint32_t*)&h1,
                                   *(uint32_t*)&h2, *(uint32_t*)&h3);
}

// =================== mma / cp.async / ldmatrix helpers ===================
__device__ __forceinline__ void mma_f16(float* d, const uint32_t* a, const uint32_t* b) {
    asm volatile(
        "mma.sync.aligned.m16n8k16.row.col.f32.f16.f16.f32 "
        "{%0,%1,%2,%3}, {%4,%5,%6,%7}, {%8,%9}, {%0,%1,%2,%3};"
        : "+f"(d[0]), "+f"(d[1]), "+f"(d[2]), "+f"(d[3])
        : "r"(a[0]), "r"(a[1]), "r"(a[2]), "r"(a[3]),
          "r"(b[0]), "r"(b[1]));
}
__device__ __forceinline__ uint32_t smem_u32(const void* p) {
    uint32_t a;
    asm("{ .reg .u64 t; cvta.to.shared.u64 t, %1; cvt.u32.u64 %0, t; }" : "=r"(a) : "l"(p));
    return a;
}
#define LDSM_X4(r0, r1, r2, r3, addr)                                        \
    asm volatile("ldmatrix.sync.aligned.m8n8.x4.shared.b16 {%0,%1,%2,%3}, [%4];" \
        : "=r"(r0), "=r"(r1), "=r"(r2), "=r"(r3) : "r"(addr))
#define CP_ASYNC16(dst, src) \
    asm volatile("cp.async.cg.shared.global [%0], [%1], 16;" :: "r"(dst), "l"(src))
#define CP_COMMIT() asm volatile("cp.async.commit_group;" ::: "memory")
#define CP_WAIT0()  asm volatile("cp.async.wait_group 0;" ::: "memory")
#define CP_WAIT1()  asm volatile("cp.async.wait_group 1;" ::: "memory")

// =================== kernel: xt = xh @ Wh  (R7 fp16 mma + ldmatrix, BK=64) ===
#define BM 128
#define BN 128
#define BK 64
#define NCH (FC / BK)            // 4
#define TILE_B  (128 * 128)      // 16 KB per (A or B) tile
#define STAGE_B (2 * TILE_B)     // 32 KB
#define A_OFF(p) ((p) * STAGE_B)
#define B_OFF(p) ((p) * STAGE_B + TILE_B)
#define GEMM_SMEM (2 * STAGE_B)  // 64 KB

__global__ __launch_bounds__(256, 2) void k_gemm(int row_base) {
    extern __shared__ char sm[];
    const uint32_t sb = smem_u32(sm);

    const int tid  = threadIdx.x;
    const int lane = tid & 31;
    const int wid  = tid >> 5;
    const int wm = (wid & 1) * 64;
    const int wn = (wid >> 1) * 32;
    const int bm = row_base + blockIdx.x * BM;
    const int bn = blockIdx.y * BN;
    const int g  = lane >> 2;
    const int tg = lane & 3;

    const int cp_row = tid >> 3;
    const int cp_c   = tid & 7;

    const int a_lrow  = lane & 15;
    const int a_lchnk = lane >> 4;
    const int b_lrow  = ((lane >> 4) << 3) + (lane & 7);
    const int b_lchnk = (lane >> 3) & 1;

    float acc[4][4][4];
#pragma unroll
    for (int mt = 0; mt < 4; mt++)
#pragma unroll
        for (int nt = 0; nt < 4; nt++)
#pragma unroll
            for (int r = 0; r < 4; r++) acc[mt][nt][r] = 0.0f;

    auto issue = [&](int c, int p) {
        const int k0 = c * BK;
#pragma unroll
        for (int q = 0; q < 4; q++) {          // A: 128 rows x 64 halves
            int row = q * 32 + cp_row;
            uint32_t dst = sb + A_OFF(p) + row * 128 + ((cp_c ^ (row & 7)) << 4);
            CP_ASYNC16(dst, &g_xh[(size_t)(bm + row) * FC + k0 + cp_c * 8]);
        }
#pragma unroll
        for (int q = 0; q < 4; q++) {          // B: 128 rows x 64 halves
            int row = q * 32 + cp_row;
            uint32_t dst = sb + B_OFF(p) + row * 128 + ((cp_c ^ (row & 7)) << 4);
            CP_ASYNC16(dst, &g_wh[(size_t)(bn + row) * FC + k0 + cp_c * 8]);
        }
        CP_COMMIT();
    };

    issue(0, 0);
    issue(1, 1);

#pragma unroll
    for (int c = 0; c < NCH; c++) {
        const int p = c & 1;
        if (c == NCH - 1) { CP_WAIT0(); } else { CP_WAIT1(); }
        __syncthreads();

        const uint32_t sA = sb + A_OFF(p);
        const uint32_t sB = sb + B_OFF(p);

#pragma unroll
        for (int s = 0; s < 4; s++) {
            uint32_t a[4][4], b[4][2];
#pragma unroll
            for (int mt = 0; mt < 4; mt++) {
                int row = wm + mt * 16 + a_lrow;
                int ch  = (s * 2 + a_lchnk) ^ (row & 7);
                LDSM_X4(a[mt][0], a[mt][1], a[mt][2], a[mt][3],
                        sA + row * 128 + (ch << 4));
            }
#pragma unroll
            for (int pr = 0; pr < 2; pr++) {
                int row = wn + pr * 16 + b_lrow;
                int ch  = (s * 2 + b_lchnk) ^ (row & 7);
                LDSM_X4(b[pr * 2][0], b[pr * 2][1], b[pr * 2 + 1][0], b[pr * 2 + 1][1],
                        sB + row * 128 + (ch << 4));
            }
#pragma unroll
            for (int mt = 0; mt < 4; mt++)
#pragma unroll
                for (int nt = 0; nt < 4; nt++)
                    mma_f16(acc[mt][nt], a[mt], b[nt]);
        }
        __syncthreads();
        if (c + 2 < NCH) issue(c + 2, p);
    }

#pragma unroll
    for (int mt = 0; mt < 4; mt++) {
#pragma unroll
        for (int nt = 0; nt < 4; nt++) {
            int r = bm + wm + mt * 16 + g;
            int c = bn + wn + nt * 8 + tg * 2;
            __half2 h01 = __floats2half2_rn(acc[mt][nt][0], acc[mt][nt][1]);
            __half2 h23 = __floats2half2_rn(acc[mt][nt][2], acc[mt][nt][3]);
            *(__half2*)&g_xt[(size_t)r * FC + c]       = h01;
            *(__half2*)&g_xt[(size_t)(r + 8) * FC + c] = h23;
        }
    }
}

// =================== kernel: aggregate, 4 batches per launch ===================
// block = node i, 128 threads: batch b0+(t>>5), features (t&31)*8 (LDG.128/nbr)
__global__ __launch_bounds__(128) void k_aggregate4(const float* __restrict__ bias,
                                                    float* __restrict__ out, int b0) {
    __shared__ int s_nbr[NN];
    __shared__ int s_off[WORDS];
    __shared__ int s_total;

    const int i = blockIdx.x;
    const int t = threadIdx.x;
    const int b  = b0 + (t >> 5);
    const int f8 = (t & 31) * 8;

    uint32_t word = g_adj[i * WORDS + t];   // 128 threads = 128 words exactly
    s_off[t] = __popc(word);
    __syncthreads();

    if (t < 32) {   // warp 0: exclusive scan of 128 popcounts
        int v0 = s_off[4 * t], v1 = s_off[4 * t + 1];
        int v2 = s_off[4 * t + 2], v3 = s_off[4 * t + 3];
        int sum = v0 + v1 + v2 + v3;
        int inc = sum;
#pragma unroll
        for (int d = 1; d < 32; d <<= 1) {
            int x = __shfl_up_sync(0xFFFFFFFFu, inc, d);
            if (t >= d) inc += x;
        }
        int exc = inc - sum;
        s_off[4 * t]     = exc;
        s_off[4 * t + 1] = exc + v0;
        s_off[4 * t + 2] = exc + v0 + v1;
        s_off[4 * t + 3] = exc + v0 + v1 + v2;
        if (t == 31) s_total = inc;
    }
    __syncthreads();

    {   // deterministic expansion, 1 word per thread
        int pos = s_off[t];
        uint32_t m = word;
        while (m) {
            int bit = __ffs(m) - 1;
            m &= m - 1;
            s_nbr[pos++] = t * 32 + bit;
        }
    }
    __syncthreads();

    const int n = s_total;
    const float inv = 1.0f / ((float)n + 1e-6f);
    const __half* __restrict__ xb = g_xt + (size_t)b * NN * FC + f8;

    float a0 = 0.f, a1 = 0.f, a2 = 0.f, a3 = 0.f;
    float a4 = 0.f, a5 = 0.f, a6 = 0.f, a7 = 0.f;

#define ACC8(v)                                               \
    do { const __half2* _h = (const __half2*)&(v); float2 _p; \
        _p = __half22float2(_h[0]); a0 += _p.x; a1 += _p.y;   \
        _p = __half22float2(_h[1]); a2 += _p.x; a3 += _p.y;   \
        _p = __half22float2(_h[2]); a4 += _p.x; a5 += _p.y;   \
        _p = __half22float2(_h[3]); a6 += _p.x; a7 += _p.y; } while (0)

    int k = 0;
    for (; k + 4 <= n; k += 4) {
        uint4 v0 = *(const uint4*)&xb[(size_t)s_nbr[k]     * FC];
        uint4 v1 = *(const uint4*)&xb[(size_t)s_nbr[k + 1] * FC];
        uint4 v2 = *(const uint4*)&xb[(size_t)s_nbr[k + 2] * FC];
        uint4 v3 = *(const uint4*)&xb[(size_t)s_nbr[k + 3] * FC];
        ACC8(v0); ACC8(v1); ACC8(v2); ACC8(v3);
    }
    for (; k < n; k++) {
        uint4 v0 = *(const uint4*)&xb[(size_t)s_nbr[k] * FC];
        ACC8(v0);
    }
#undef ACC8

    float4 bl = *(const float4*)&bias[f8];
    float4 bh = *(const float4*)&bias[f8 + 4];
    float* o = out + ((size_t)b * NN + i) * FC + f8;
    *(float4*)o       = make_float4(a0 * inv + bl.x, a1 * inv + bl.y,
                                    a2 * inv + bl.z, a3 * inv + bl.w);
    *(float4*)(o + 4) = make_float4(a4 * inv + bh.x, a5 * inv + bh.y,
                                    a6 * inv + bh.z, a7 * inv + bh.w);
}

// =================== launch ===================
extern "C" void kernel_launch(void* const* d_in, const int* in_sizes, int n_in,
                              void* d_out, int out_size) {
    const float* x    = (const float*)d_in[0];
    const int*   ei   = (const int*)d_in[1];
    const float* w    = (const float*)d_in[2];
    const float* bias = (const float*)d_in[3];
    float*       out  = (float*)d_out;

    const int E = in_sizes[1] / 2;
    const int CVT_BLKS = 4 * NN * FC / (256 * 8);   // 2048 per 4-batch half

    cudaFuncSetAttribute(k_gemm, cudaFuncAttributeMaxDynamicSharedMemorySize,
                         GEMM_SMEM);

    dim3 wt_tb(32, 8), wt_tg(FC / 32, FC / 32);
    dim3 ggrid(4 * NN / BM, FC / BN);   // 128 x 2 = 256 CTAs per half

    if (g_ok) {
        cudaEventRecord(g_evFork, 0);
        cudaStreamWaitEvent(g_s1, g_evFork, 0);
        cudaStreamWaitEvent(g_s2, g_evFork, 0);

        // s2: adjacency setup (feeds only the aggregates)
        k_clear_adj<<<(NN * WORDS + 255) / 256, 256, 0, g_s2>>>();
        k_scatter<<<(E + 255) / 256, 256, 0, g_s2>>>(ei, E);

        // s1: weight prep + half 0
        k_wt<<<wt_tg, wt_tb, 0, g_s1>>>(w);
        k_cvt<<<CVT_BLKS, 256, 0, g_s1>>>(x, 0);
        k_gemm<<<ggrid, 256, GEMM_SMEM, g_s1>>>(0);
        cudaEventRecord(g_evG[0], g_s1);

        // s1: half 1 (overlaps agg half 0 on s2)
        k_cvt<<<CVT_BLKS, 256, 0, g_s1>>>(x, 4);
        k_gemm<<<ggrid, 256, GEMM_SMEM, g_s1>>>(4 * NN);
        cudaEventRecord(g_evG[1], g_s1);

        // s2: aggregates
        cudaStreamWaitEvent(g_s2, g_evG[0], 0);
        k_aggregate4<<<NN, 128, 0, g_s2>>>(bias, out, 0);
        cudaStreamWaitEvent(g_s2, g_evG[1], 0);
        k_aggregate4<<<NN, 128, 0, g_s2>>>(bias, out, 4);

        // join
        cudaEventRecord(g_evJ, g_s2);
        cudaStreamWaitEvent(0, g_evG[1], 0);
        cudaStreamWaitEvent(0, g_evJ, 0);
    } else {
        // serial fallback: identical math
        k_clear_adj<<<(NN * WORDS + 255) / 256, 256, 0, 0>>>();
        k_scatter<<<(E + 255) / 256, 256, 0, 0>>>(ei, E);
        k_wt<<<wt_tg, wt_tb, 0, 0>>>(w);
        for (int h = 0; h < NHALF; h++) {
            k_cvt<<<CVT_BLKS, 256, 0, 0>>>(x, 4 * h);
            k_gemm<<<ggrid, 256, GEMM_SMEM, 0>>>(4 * h * NN);
            k_aggregate4<<<NN, 128, 0, 0>>>(bias, out, 4 * h);
        }
    }
}

// round 12
// speedup vs baseline: 1.2504x; 1.0473x over previous
#include <cuda_runtime.h>
#include <cuda_fp16.h>
#include <stdint.h>

#define NN 4096
#define FC 256      // F_IN == F_OUT
#define BB 8
#define WORDS (NN / 32)

// ---------------- scratch (no allocations allowed) ----------------
__device__ uint32_t g_adj[NN * WORDS];            // 2 MB bitmask adjacency
__device__ __half   g_xt[(size_t)BB * NN * FC];   // 16 MB: xt = x @ W (fp16)
__device__ __half   g_xh[(size_t)BB * NN * FC];   // 16 MB: x as fp16
__device__ __half   g_wh[FC * FC];                // 128 KB: W^T as fp16 [n][k]

// =================== setup kernels ===================
// clear 2MB adjacency: 8 words (32B) per thread, uint4 stores
__global__ __launch_bounds__(256) void k_clear_adj() {
    const int i = (blockIdx.x * 256 + threadIdx.x) * 8;
    *(uint4*)&g_adj[i]     = make_uint4(0u, 0u, 0u, 0u);
    *(uint4*)&g_adj[i + 4] = make_uint4(0u, 0u, 0u, 0u);
}
// scatter: 4 edges per thread, batched independent loads for MLP
__global__ __launch_bounds__(256) void k_scatter(const int* __restrict__ ei, int E) {
    const int e0 = (blockIdx.x * 256 + threadIdx.x) * 4;
    int s0 = ei[e0], s1 = ei[e0 + 1], s2 = ei[e0 + 2], s3 = ei[e0 + 3];
    int d0 = ei[E + e0], d1 = ei[E + e0 + 1], d2 = ei[E + e0 + 2], d3 = ei[E + e0 + 3];
    atomicOr(&g_adj[s0 * WORDS + (d0 >> 5)], 1u << (d0 & 31));
    atomicOr(&g_adj[s1 * WORDS + (d1 >> 5)], 1u << (d1 & 31));
    atomicOr(&g_adj[s2 * WORDS + (d2 >> 5)], 1u << (d2 & 31));
    atomicOr(&g_adj[s3 * WORDS + (d3 >> 5)], 1u << (d3 & 31));
}
// W[k][n] -> g_wh[n][k] fp16 (tiled transpose, coalesced)
__global__ void k_wt(const float* __restrict__ W) {
    __shared__ float tile[32][33];
    const int bn = blockIdx.x * 32;
    const int bk = blockIdx.y * 32;
    const int tx = threadIdx.x, ty = threadIdx.y;
#pragma unroll
    for (int r = ty; r < 32; r += 8)
        tile[r][tx] = W[(size_t)(bk + r) * FC + bn + tx];
    __syncthreads();
#pragma unroll
    for (int r = ty; r < 32; r += 8)
        g_wh[(size_t)(bn + r) * FC + bk + tx] = __float2half_rn(tile[tx][r]);
}
// x (fp32) -> g_xh (fp16): 16 elements/thread (4 independent LDG.128, MLP=4)
__global__ __launch_bounds__(256) void k_cvt(const float* __restrict__ x) {
    const size_t i = ((size_t)blockIdx.x * 256 + threadIdx.x) * 16;
    float4 v0 = *(const float4*)&x[i];
    float4 v1 = *(const float4*)&x[i + 4];
    float4 v2 = *(const float4*)&x[i + 8];
    float4 v3 = *(const float4*)&x[i + 12];
    __half2 h0 = __floats2half2_rn(v0.x, v0.y);
    __half2 h1 = __floats2half2_rn(v0.z, v0.w);
    __half2 h2 = __floats2half2_rn(v1.x, v1.y);
    __half2 h3 = __floats2half2_rn(v1.z, v1.w);
    __half2 h4 = __floats2half2_rn(v2.x, v2.y);
    __half2 h5 = __floats2half2_rn(v2.z, v2.w);
    __half2 h6 = __floats2half2_rn(v3.x, v3.y);
    __half2 h7 = __floats2half2_rn(v3.z, v3.w);
    *(uint4*)&g_xh[i]     = make_uint4(*(uint32_t*)&h0, *(uint32_t*)&h1,
                                       *(uint32_t*)&h2, *(uint32_t*)&h3);
    *(uint4*)&g_xh[i + 8] = make_uint4(*(uint32_t*)&h4, *(uint32_t*)&h5,
                                       *(uint32_t*)&h6, *(uint32_t*)&h7);
}

// =================== mma / cp.async / ldmatrix helpers ===================
__device__ __forceinline__ void mma_f16(float* d, const uint32_t* a, const uint32_t* b) {
    asm volatile(
        "mma.sync.aligned.m16n8k16.row.col.f32.f16.f16.f32 "
        "{%0,%1,%2,%3}, {%4,%5,%6,%7}, {%8,%9}, {%0,%1,%2,%3};"
        : "+f"(d[0]), "+f"(d[1]), "+f"(d[2]), "+f"(d[3])
        : "r"(a[0]), "r"(a[1]), "r"(a[2]), "r"(a[3]),
          "r"(b[0]), "r"(b[1]));
}
__device__ __forceinline__ uint32_t smem_u32(const void* p) {
    uint32_t a;
    asm("{ .reg .u64 t; cvta.to.shared.u64 t, %1; cvt.u32.u64 %0, t; }" : "=r"(a) : "l"(p));
    return a;
}
#define LDSM_X4(r0, r1, r2, r3, addr)                                        \
    asm volatile("ldmatrix.sync.aligned.m8n8.x4.shared.b16 {%0,%1,%2,%3}, [%4];" \
        : "=r"(r0), "=r"(r1), "=r"(r2), "=r"(r3) : "r"(addr))
#define CP_ASYNC16(dst, src) \
    asm volatile("cp.async.cg.shared.global [%0], [%1], 16;" :: "r"(dst), "l"(src))
#define CP_COMMIT() asm volatile("cp.async.commit_group;" ::: "memory")
#define CP_WAIT0()  asm volatile("cp.async.wait_group 0;" ::: "memory")
#define CP_WAIT1()  asm volatile("cp.async.wait_group 1;" ::: "memory")

// =================== kernel: xt = xh @ Wh  (R7 fp16 mma + ldmatrix, BK=64) ===
#define BM 128
#define BN 128
#define BK 64
#define NCH (FC / BK)            // 4
#define TILE_B  (128 * 128)      // 16 KB per (A or B) tile
#define STAGE_B (2 * TILE_B)     // 32 KB
#define A_OFF(p) ((p) * STAGE_B)
#define B_OFF(p) ((p) * STAGE_B + TILE_B)
#define GEMM_SMEM (2 * STAGE_B)  // 64 KB

__global__ __launch_bounds__(256, 2) void k_gemm() {
    extern __shared__ char sm[];
    const uint32_t sb = smem_u32(sm);

    const int tid  = threadIdx.x;
    const int lane = tid & 31;
    const int wid  = tid >> 5;
    const int wm = (wid & 1) * 64;
    const int wn = (wid >> 1) * 32;
    const int bm = blockIdx.x * BM;
    const int bn = blockIdx.y * BN;
    const int g  = lane >> 2;
    const int tg = lane & 3;

    const int cp_row = tid >> 3;
    const int cp_c   = tid & 7;

    const int a_lrow  = lane & 15;
    const int a_lchnk = lane >> 4;
    const int b_lrow  = ((lane >> 4) << 3) + (lane & 7);
    const int b_lchnk = (lane >> 3) & 1;

    float acc[4][4][4];
#pragma unroll
    for (int mt = 0; mt < 4; mt++)
#pragma unroll
        for (int nt = 0; nt < 4; nt++)
#pragma unroll
            for (int r = 0; r < 4; r++) acc[mt][nt][r] = 0.0f;

    auto issue = [&](int c, int p) {
        const int k0 = c * BK;
#pragma unroll
        for (int q = 0; q < 4; q++) {          // A: 128 rows x 64 halves
            int row = q * 32 + cp_row;
            uint32_t dst = sb + A_OFF(p) + row * 128 + ((cp_c ^ (row & 7)) << 4);
            CP_ASYNC16(dst, &g_xh[(size_t)(bm + row) * FC + k0 + cp_c * 8]);
        }
#pragma unroll
        for (int q = 0; q < 4; q++) {          // B: 128 rows x 64 halves
            int row = q * 32 + cp_row;
            uint32_t dst = sb + B_OFF(p) + row * 128 + ((cp_c ^ (row & 7)) << 4);
            CP_ASYNC16(dst, &g_wh[(size_t)(bn + row) * FC + k0 + cp_c * 8]);
        }
        CP_COMMIT();
    };

    issue(0, 0);
    issue(1, 1);

#pragma unroll
    for (int c = 0; c < NCH; c++) {
        const int p = c & 1;
        if (c == NCH - 1) { CP_WAIT0(); } else { CP_WAIT1(); }
        __syncthreads();

        const uint32_t sA = sb + A_OFF(p);
        const uint32_t sB = sb + B_OFF(p);

#pragma unroll
        for (int s = 0; s < 4; s++) {
            uint32_t a[4][4], b[4][2];
#pragma unroll
            for (int mt = 0; mt < 4; mt++) {
                int row = wm + mt * 16 + a_lrow;
                int ch  = (s * 2 + a_lchnk) ^ (row & 7);
                LDSM_X4(a[mt][0], a[mt][1], a[mt][2], a[mt][3],
                        sA + row * 128 + (ch << 4));
            }
#pragma unroll
            for (int pr = 0; pr < 2; pr++) {
                int row = wn + pr * 16 + b_lrow;
                int ch  = (s * 2 + b_lchnk) ^ (row & 7);
                LDSM_X4(b[pr * 2][0], b[pr * 2][1], b[pr * 2 + 1][0], b[pr * 2 + 1][1],
                        sB + row * 128 + (ch << 4));
            }
#pragma unroll
            for (int mt = 0; mt < 4; mt++)
#pragma unroll
                for (int nt = 0; nt < 4; nt++)
                    mma_f16(acc[mt][nt], a[mt], b[nt]);
        }
        __syncthreads();
        if (c + 2 < NCH) issue(c + 2, p);
    }

#pragma unroll
    for (int mt = 0; mt < 4; mt++) {
#pragma unroll
        for (int nt = 0; nt < 4; nt++) {
            int r = bm + wm + mt * 16 + g;
            int c = bn + wn + nt * 8 + tg * 2;
            __half2 h01 = __floats2half2_rn(acc[mt][nt][0], acc[mt][nt][1]);
            __half2 h23 = __floats2half2_rn(acc[mt][nt][2], acc[mt][nt][3]);
            *(__half2*)&g_xt[(size_t)r * FC + c]       = h01;
            *(__half2*)&g_xt[(size_t)(r + 8) * FC + c] = h23;
        }
    }
}

// =================== kernel: aggregate (R7: 8 batches/block) ===================
// thread t: batch b = t>>5, features f8 = (t&31)*8 (one LDG.128 / neighbor)
__global__ __launch_bounds__(256) void k_aggregate(const float* __restrict__ bias,
                                                   float* __restrict__ out) {
    __shared__ int s_nbr[NN];
    __shared__ int s_off[WORDS];
    __shared__ int s_total;

    const int i = blockIdx.x;
    const int t = threadIdx.x;
    const int b  = t >> 5;
    const int f8 = (t & 31) * 8;

    uint32_t word = (t < WORDS) ? g_adj[i * WORDS + t] : 0u;
    if (t < WORDS) s_off[t] = __popc(word);
    __syncthreads();

    if (t < 32) {   // warp 0: exclusive scan of 128 popcounts
        int v0 = s_off[4 * t], v1 = s_off[4 * t + 1];
        int v2 = s_off[4 * t + 2], v3 = s_off[4 * t + 3];
        int sum = v0 + v1 + v2 + v3;
        int inc = sum;
#pragma unroll
        for (int d = 1; d < 32; d <<= 1) {
            int x = __shfl_up_sync(0xFFFFFFFFu, inc, d);
            if (t >= d) inc += x;
        }
        int exc = inc - sum;
        s_off[4 * t]     = exc;
        s_off[4 * t + 1] = exc + v0;
        s_off[4 * t + 2] = exc + v0 + v1;
        s_off[4 * t + 3] = exc + v0 + v1 + v2;
        if (t == 31) s_total = inc;
    }
    __syncthreads();

    if (t < WORDS) {
        int pos = s_off[t];
        uint32_t m = word;
        while (m) {
            int bit = __ffs(m) - 1;
            m &= m - 1;
            s_nbr[pos++] = t * 32 + bit;
        }
    }
    __syncthreads();

    const int n = s_total;
    const float inv = 1.0f / ((float)n + 1e-6f);
    const __half* __restrict__ xb = g_xt + (size_t)b * NN * FC + f8;

    float a0 = 0.f, a1 = 0.f, a2 = 0.f, a3 = 0.f;
    float a4 = 0.f, a5 = 0.f, a6 = 0.f, a7 = 0.f;

#define ACC8(v)                                               \
    do { const __half2* _h = (const __half2*)&(v); float2 _p; \
        _p = __half22float2(_h[0]); a0 += _p.x; a1 += _p.y;   \
        _p = __half22float2(_h[1]); a2 += _p.x; a3 += _p.y;   \
        _p = __half22float2(_h[2]); a4 += _p.x; a5 += _p.y;   \
        _p = __half22float2(_h[3]); a6 += _p.x; a7 += _p.y; } while (0)

    int k = 0;
    for (; k + 4 <= n; k += 4) {
        uint4 v0 = *(const uint4*)&xb[(size_t)s_nbr[k]     * FC];
        uint4 v1 = *(const uint4*)&xb[(size_t)s_nbr[k + 1] * FC];
        uint4 v2 = *(const uint4*)&xb[(size_t)s_nbr[k + 2] * FC];
        uint4 v3 = *(const uint4*)&xb[(size_t)s_nbr[k + 3] * FC];
        ACC8(v0); ACC8(v1); ACC8(v2); ACC8(v3);
    }
    for (; k < n; k++) {
        uint4 v0 = *(const uint4*)&xb[(size_t)s_nbr[k] * FC];
        ACC8(v0);
    }
#undef ACC8

    float4 bl = *(const float4*)&bias[f8];
    float4 bh = *(const float4*)&bias[f8 + 4];
    float* o = out + ((size_t)b * NN + i) * FC + f8;
    *(float4*)o       = make_float4(a0 * inv + bl.x, a1 * inv + bl.y,
                                    a2 * inv + bl.z, a3 * inv + bl.w);
    *(float4*)(o + 4) = make_float4(a4 * inv + bh.x, a5 * inv + bh.y,
                                    a6 * inv + bh.z, a7 * inv + bh.w);
}

// =================== launch ===================
extern "C" void kernel_launch(void* const* d_in, const int* in_sizes, int n_in,
                              void* d_out, int out_size) {
    const float* x    = (const float*)d_in[0];
    const int*   ei   = (const int*)d_in[1];
    const float* w    = (const float*)d_in[2];
    const float* bias = (const float*)d_in[3];
    float*       out  = (float*)d_out;

    const int E = in_sizes[1] / 2;
    const int M = BB * NN;

    cudaFuncSetAttribute(k_gemm, cudaFuncAttributeMaxDynamicSharedMemorySize,
                         GEMM_SMEM);

    k_clear_adj<<<NN * WORDS / (256 * 8), 256>>>();       // 256 blocks
    k_scatter<<<E / (256 * 4), 256>>>(ei, E);             // 128 blocks
    {
        dim3 tb(32, 8);
        dim3 tg(FC / 32, FC / 32);
        k_wt<<<tg, tb>>>(w);
    }
    k_cvt<<<(int)((size_t)M * FC / (256 * 16)), 256>>>(x);  // 2048 blocks

    dim3 ggrid(M / BM, FC / BN);
    k_gemm<<<ggrid, 256, GEMM_SMEM>>>();

    k_aggregate<<<NN, 256>>>(bias, out);
}

// round 13
// speedup vs baseline: 1.2554x; 1.0040x over previous
#include <cuda_runtime.h>
#include <cuda_fp16.h>
#include <stdint.h>

#define NN 4096
#define FC 256      // F_IN == F_OUT
#define BB 8
#define WORDS (NN / 32)

// ---------------- scratch (no allocations allowed) ----------------
__device__ uint32_t g_adj[NN * WORDS];            // 2 MB bitmask adjacency
__device__ __half   g_xt[(size_t)BB * NN * FC];   // 16 MB: xt = x @ W (fp16)
__device__ __half   g_xh[(size_t)BB * NN * FC];   // 16 MB: x as fp16
__device__ __half   g_wh[FC * FC];                // 128 KB: W^T as fp16 [n][k]

// =================== setup kernels ===================
__global__ __launch_bounds__(256) void k_clear_adj() {
    const int i = (blockIdx.x * 256 + threadIdx.x) * 8;
    *(uint4*)&g_adj[i]     = make_uint4(0u, 0u, 0u, 0u);
    *(uint4*)&g_adj[i + 4] = make_uint4(0u, 0u, 0u, 0u);
}
__global__ __launch_bounds__(256) void k_scatter(const int* __restrict__ ei, int E) {
    const int e0 = (blockIdx.x * 256 + threadIdx.x) * 4;
    int s0 = ei[e0], s1 = ei[e0 + 1], s2 = ei[e0 + 2], s3 = ei[e0 + 3];
    int d0 = ei[E + e0], d1 = ei[E + e0 + 1], d2 = ei[E + e0 + 2], d3 = ei[E + e0 + 3];
    atomicOr(&g_adj[s0 * WORDS + (d0 >> 5)], 1u << (d0 & 31));
    atomicOr(&g_adj[s1 * WORDS + (d1 >> 5)], 1u << (d1 & 31));
    atomicOr(&g_adj[s2 * WORDS + (d2 >> 5)], 1u << (d2 & 31));
    atomicOr(&g_adj[s3 * WORDS + (d3 >> 5)], 1u << (d3 & 31));
}
// W[k][n] -> g_wh[n][k] fp16 (tiled transpose, coalesced)
__global__ void k_wt(const float* __restrict__ W) {
    __shared__ float tile[32][33];
    const int bn = blockIdx.x * 32;
    const int bk = blockIdx.y * 32;
    const int tx = threadIdx.x, ty = threadIdx.y;
#pragma unroll
    for (int r = ty; r < 32; r += 8)
        tile[r][tx] = W[(size_t)(bk + r) * FC + bn + tx];
    __syncthreads();
#pragma unroll
    for (int r = ty; r < 32; r += 8)
        g_wh[(size_t)(bn + r) * FC + bk + tx] = __float2half_rn(tile[tx][r]);
}
// x (fp32) -> g_xh (fp16): R7's measured-best shape (8 elems/thread)
__global__ __launch_bounds__(256) void k_cvt(const float* __restrict__ x) {
    const size_t i = ((size_t)blockIdx.x * 256 + threadIdx.x) * 8;
    float4 v0 = *(const float4*)&x[i];
    float4 v1 = *(const float4*)&x[i + 4];
    __half2 h0 = __floats2half2_rn(v0.x, v0.y);
    __half2 h1 = __floats2half2_rn(v0.z, v0.w);
    __half2 h2 = __floats2half2_rn(v1.x, v1.y);
    __half2 h3 = __floats2half2_rn(v1.z, v1.w);
    *(uint4*)&g_xh[i] = make_uint4(*(uint32_t*)&h0, *(uint32_t*)&h1,
                                   *(uint32_t*)&h2, *(uint32_t*)&h3);
}

// =================== mma / cp.async / ldmatrix helpers ===================
__device__ __forceinline__ void mma_f16(float* d, const uint32_t* a, const uint32_t* b) {
    asm volatile(
        "mma.sync.aligned.m16n8k16.row.col.f32.f16.f16.f32 "
        "{%0,%1,%2,%3}, {%4,%5,%6,%7}, {%8,%9}, {%0,%1,%2,%3};"
        : "+f"(d[0]), "+f"(d[1]), "+f"(d[2]), "+f"(d[3])
        : "r"(a[0]), "r"(a[1]), "r"(a[2]), "r"(a[3]),
          "r"(b[0]), "r"(b[1]));
}
__device__ __forceinline__ uint32_t smem_u32(const void* p) {
    uint32_t a;
    asm("{ .reg .u64 t; cvta.to.shared.u64 t, %1; cvt.u32.u64 %0, t; }" : "=r"(a) : "l"(p));
    return a;
}
#define LDSM_X4(r0, r1, r2, r3, addr)                                        \
    asm volatile("ldmatrix.sync.aligned.m8n8.x4.shared.b16 {%0,%1,%2,%3}, [%4];" \
        : "=r"(r0), "=r"(r1), "=r"(r2), "=r"(r3) : "r"(addr))
#define CP_ASYNC16(dst, src) \
    asm volatile("cp.async.cg.shared.global [%0], [%1], 16;" :: "r"(dst), "l"(src))
#define CP_COMMIT() asm volatile("cp.async.commit_group;" ::: "memory")
#define CP_WAIT0()  asm volatile("cp.async.wait_group 0;" ::: "memory")
#define CP_WAIT1()  asm volatile("cp.async.wait_group 1;" ::: "memory")

// =================== kernel: xt = xh @ Wh  (BN=256, 512 threads) ===========
// Block tile 128x256 (full N), BK=64, 16 warps as 2(m)x8(n), warp tile 64x32
// (per-warp inner loop identical to R7). 2-stage cp.async pipeline.
#define BM 128
#define BN 256
#define BK 64
#define NCH (FC / BK)            // 4
#define A_TILE_B  (128 * 128)    // 16 KB A tile (fp16, 128 rows x 64 halves)
#define B_TILE_B  (256 * 128)    // 32 KB B tile (fp16, 256 rows x 64 halves)
#define STAGE_B   (A_TILE_B + B_TILE_B)   // 48 KB
#define A_OFF(p)  ((p) * STAGE_B)
#define B_OFF(p)  ((p) * STAGE_B + A_TILE_B)
#define GEMM_SMEM (2 * STAGE_B)  // 96 KB

__global__ __launch_bounds__(512, 1) void k_gemm() {
    extern __shared__ char sm[];
    const uint32_t sb = smem_u32(sm);

    const int tid  = threadIdx.x;
    const int lane = tid & 31;
    const int wid  = tid >> 5;             // 0..15
    const int wm = (wid & 1) * 64;         // 2 warps in m
    const int wn = (wid >> 1) * 32;        // 8 warps in n -> 256
    const int bm = blockIdx.x * BM;

    const int g  = lane >> 2;
    const int tg = lane & 3;

    const int a_lrow  = lane & 15;
    const int a_lchnk = lane >> 4;
    const int b_lrow  = ((lane >> 4) << 3) + (lane & 7);
    const int b_lchnk = (lane >> 3) & 1;

    float acc[4][4][4];
#pragma unroll
    for (int mt = 0; mt < 4; mt++)
#pragma unroll
        for (int nt = 0; nt < 4; nt++)
#pragma unroll
            for (int r = 0; r < 4; r++) acc[mt][nt][r] = 0.0f;

    auto issue = [&](int c, int p) {
        const int k0 = c * BK;
#pragma unroll
        for (int q = 0; q < 2; q++) {      // A: 128 rows x 64 halves (1024 x 16B)
            int id  = q * 512 + tid;
            int row = id >> 3;
            int ch  = id & 7;
            uint32_t dst = sb + A_OFF(p) + row * 128 + ((ch ^ (row & 7)) << 4);
            CP_ASYNC16(dst, &g_xh[(size_t)(bm + row) * FC + k0 + ch * 8]);
        }
#pragma unroll
        for (int q = 0; q < 4; q++) {      // B: 256 rows x 64 halves (2048 x 16B)
            int id  = q * 512 + tid;
            int row = id >> 3;
            int ch  = id & 7;
            uint32_t dst = sb + B_OFF(p) + row * 128 + ((ch ^ (row & 7)) << 4);
            CP_ASYNC16(dst, &g_wh[(size_t)row * FC + k0 + ch * 8]);
        }
        CP_COMMIT();
    };

    issue(0, 0);
    issue(1, 1);

#pragma unroll
    for (int c = 0; c < NCH; c++) {
        const int p = c & 1;
        if (c == NCH - 1) { CP_WAIT0(); } else { CP_WAIT1(); }
        __syncthreads();

        const uint32_t sA = sb + A_OFF(p);
        const uint32_t sB = sb + B_OFF(p);

#pragma unroll
        for (int s = 0; s < 4; s++) {
            uint32_t a[4][4], b[4][2];
#pragma unroll
            for (int mt = 0; mt < 4; mt++) {
                int row = wm + mt * 16 + a_lrow;
                int ch  = (s * 2 + a_lchnk) ^ (row & 7);
                LDSM_X4(a[mt][0], a[mt][1], a[mt][2], a[mt][3],
                        sA + row * 128 + (ch << 4));
            }
#pragma unroll
            for (int pr = 0; pr < 2; pr++) {
                int row = wn + pr * 16 + b_lrow;
                int ch  = (s * 2 + b_lchnk) ^ (row & 7);
                LDSM_X4(b[pr * 2][0], b[pr * 2][1], b[pr * 2 + 1][0], b[pr * 2 + 1][1],
                        sB + row * 128 + (ch << 4));
            }
#pragma unroll
            for (int mt = 0; mt < 4; mt++)
#pragma unroll
                for (int nt = 0; nt < 4; nt++)
                    mma_f16(acc[mt][nt], a[mt], b[nt]);
        }
        __syncthreads();
        if (c + 2 < NCH) issue(c + 2, p);
    }

    // ---- epilogue: fp32 acc -> fp16 g_xt ----
#pragma unroll
    for (int mt = 0; mt < 4; mt++) {
#pragma unroll
        for (int nt = 0; nt < 4; nt++) {
            int r = bm + wm + mt * 16 + g;
            int c = wn + nt * 8 + tg * 2;
            __half2 h01 = __floats2half2_rn(acc[mt][nt][0], acc[mt][nt][1]);
            __half2 h23 = __floats2half2_rn(acc[mt][nt][2], acc[mt][nt][3]);
            *(__half2*)&g_xt[(size_t)r * FC + c]       = h01;
            *(__half2*)&g_xt[(size_t)(r + 8) * FC + c] = h23;
        }
    }
}

// =================== kernel: aggregate (unchanged, at LTS floor) ===========
// thread t: batch b = t>>5, features f8 = (t&31)*8 (one LDG.128 / neighbor)
__global__ __launch_bounds__(256) void k_aggregate(const float* __restrict__ bias,
                                                   float* __restrict__ out) {
    __shared__ int s_nbr[NN];
    __shared__ int s_off[WORDS];
    __shared__ int s_total;

    const int i = blockIdx.x;
    const int t = threadIdx.x;
    const int b  = t >> 5;
    const int f8 = (t & 31) * 8;

    uint32_t word = (t < WORDS) ? g_adj[i * WORDS + t] : 0u;
    if (t < WORDS) s_off[t] = __popc(word);
    __syncthreads();

    if (t < 32) {   // warp 0: exclusive scan of 128 popcounts
        int v0 = s_off[4 * t], v1 = s_off[4 * t + 1];
        int v2 = s_off[4 * t + 2], v3 = s_off[4 * t + 3];
        int sum = v0 + v1 + v2 + v3;
        int inc = sum;
#pragma unroll
        for (int d = 1; d < 32; d <<= 1) {
            int x = __shfl_up_sync(0xFFFFFFFFu, inc, d);
            if (t >= d) inc += x;
        }
        int exc = inc - sum;
        s_off[4 * t]     = exc;
        s_off[4 * t + 1] = exc + v0;
        s_off[4 * t + 2] = exc + v0 + v1;
        s_off[4 * t + 3] = exc + v0 + v1 + v2;
        if (t == 31) s_total = inc;
    }
    __syncthreads();

    if (t < WORDS) {
        int pos = s_off[t];
        uint32_t m = word;
        while (m) {
            int bit = __ffs(m) - 1;
            m &= m - 1;
            s_nbr[pos++] = t * 32 + bit;
        }
    }
    __syncthreads();

    const int n = s_total;
    const float inv = 1.0f / ((float)n + 1e-6f);
    const __half* __restrict__ xb = g_xt + (size_t)b * NN * FC + f8;

    float a0 = 0.f, a1 = 0.f, a2 = 0.f, a3 = 0.f;
    float a4 = 0.f, a5 = 0.f, a6 = 0.f, a7 = 0.f;

#define ACC8(v)                                               \
    do { const __half2* _h = (const __half2*)&(v); float2 _p; \
        _p = __half22float2(_h[0]); a0 += _p.x; a1 += _p.y;   \
        _p = __half22float2(_h[1]); a2 += _p.x; a3 += _p.y;   \
        _p = __half22float2(_h[2]); a4 += _p.x; a5 += _p.y;   \
        _p = __half22float2(_h[3]); a6 += _p.x; a7 += _p.y; } while (0)

    int k = 0;
    for (; k + 4 <= n; k += 4) {
        uint4 v0 = *(const uint4*)&xb[(size_t)s_nbr[k]     * FC];
        uint4 v1 = *(const uint4*)&xb[(size_t)s_nbr[k + 1] * FC];
        uint4 v2 = *(const uint4*)&xb[(size_t)s_nbr[k + 2] * FC];
        uint4 v3 = *(const uint4*)&xb[(size_t)s_nbr[k + 3] * FC];
        ACC8(v0); ACC8(v1); ACC8(v2); ACC8(v3);
    }
    for (; k < n; k++) {
        uint4 v0 = *(const uint4*)&xb[(size_t)s_nbr[k] * FC];
        ACC8(v0);
    }
#undef ACC8

    float4 bl = *(const float4*)&bias[f8];
    float4 bh = *(const float4*)&bias[f8 + 4];
    float* o = out + ((size_t)b * NN + i) * FC + f8;
    *(float4*)o       = make_float4(a0 * inv + bl.x, a1 * inv + bl.y,
                                    a2 * inv + bl.z, a3 * inv + bl.w);
    *(float4*)(o + 4) = make_float4(a4 * inv + bh.x, a5 * inv + bh.y,
                                    a6 * inv + bh.z, a7 * inv + bh.w);
}

// =================== launch ===================
extern "C" void kernel_launch(void* const* d_in, const int* in_sizes, int n_in,
                              void* d_out, int out_size) {
    const float* x    = (const float*)d_in[0];
    const int*   ei   = (const int*)d_in[1];
    const float* w    = (const float*)d_in[2];
    const float* bias = (const float*)d_in[3];
    float*       out  = (float*)d_out;

    const int E = in_sizes[1] / 2;
    const int M = BB * NN;

    cudaFuncSetAttribute(k_gemm, cudaFuncAttributeMaxDynamicSharedMemorySize,
                         GEMM_SMEM);

    k_clear_adj<<<NN * WORDS / (256 * 8), 256>>>();
    k_scatter<<<E / (256 * 4), 256>>>(ei, E);
    {
        dim3 tb(32, 8);
        dim3 tg(FC / 32, FC / 32);
        k_wt<<<tg, tb>>>(w);
    }
    k_cvt<<<(int)((size_t)M * FC / (256 * 8)), 256>>>(x);

    k_gemm<<<M / BM, 512, GEMM_SMEM>>>();

    k_aggregate<<<NN, 256>>>(bias, out);
}

// round 14
// speedup vs baseline: 1.3663x; 1.0883x over previous
#include <cuda_runtime.h>
#include <cuda_fp16.h>
#include <stdint.h>

#define NN 4096
#define FC 256      // F_IN == F_OUT
#define BB 8
#define WORDS (NN / 32)

// ---------------- scratch (no allocations allowed) ----------------
__device__ uint32_t g_adj[NN * WORDS];            // 2 MB bitmask adjacency
__device__ __half   g_xt[(size_t)BB * NN * FC];   // 16 MB: xt = x @ W (fp16)
__device__ __half   g_xh[(size_t)BB * NN * FC];   // 16 MB: x as fp16
__device__ __half   g_wh[FC * FC];                // 128 KB: W^T as fp16 [n][k]

// =================== kernel 1: clear adjacency (tiny) ===================
__global__ __launch_bounds__(256) void k_clear_adj() {
    const int i = (blockIdx.x * 256 + threadIdx.x) * 8;
    *(uint4*)&g_adj[i]     = make_uint4(0u, 0u, 0u, 0u);
    *(uint4*)&g_adj[i + 4] = make_uint4(0u, 0u, 0u, 0u);
}

// =================== kernel 2: fused scatter + wt + cvt ===================
// blocks [0, NB_CVT)               : x fp32 -> g_xh fp16 (8 elems/thread)
// blocks [NB_CVT, NB_CVT+nb_sc)    : edge scatter (4 edges/thread)
// blocks [NB_CVT+nb_sc, ...+64)    : W transpose -> g_wh fp16
#define NB_CVT 4096
__global__ __launch_bounds__(256) void k_front(const float* __restrict__ x,
                                               const int* __restrict__ ei, int E,
                                               int nb_sc,
                                               const float* __restrict__ W) {
    __shared__ float tile[32][33];
    const int bid = blockIdx.x;
    const int t   = threadIdx.x;

    if (bid < NB_CVT) {
        // ---- cvt: read-once x with streaming hint ----
        const size_t i = ((size_t)bid * 256 + t) * 8;
        float4 v0 = __ldcs((const float4*)&x[i]);
        float4 v1 = __ldcs((const float4*)&x[i + 4]);
        __half2 h0 = __floats2half2_rn(v0.x, v0.y);
        __half2 h1 = __floats2half2_rn(v0.z, v0.w);
        __half2 h2 = __floats2half2_rn(v1.x, v1.y);
        __half2 h3 = __floats2half2_rn(v1.z, v1.w);
        *(uint4*)&g_xh[i] = make_uint4(*(uint32_t*)&h0, *(uint32_t*)&h1,
                                       *(uint32_t*)&h2, *(uint32_t*)&h3);
    } else if (bid < NB_CVT + nb_sc) {
        // ---- scatter: 4 edges/thread ----
        const int e0 = ((bid - NB_CVT) * 256 + t) * 4;
        int s0 = ei[e0], s1 = ei[e0 + 1], s2 = ei[e0 + 2], s3 = ei[e0 + 3];
        int d0 = ei[E + e0], d1 = ei[E + e0 + 1];
        int d2 = ei[E + e0 + 2], d3 = ei[E + e0 + 3];
        atomicOr(&g_adj[s0 * WORDS + (d0 >> 5)], 1u << (d0 & 31));
        atomicOr(&g_adj[s1 * WORDS + (d1 >> 5)], 1u << (d1 & 31));
        atomicOr(&g_adj[s2 * WORDS + (d2 >> 5)], 1u << (d2 & 31));
        atomicOr(&g_adj[s3 * WORDS + (d3 >> 5)], 1u << (d3 & 31));
    } else {
        // ---- wt: W[k][n] -> g_wh[n][k] fp16, 32x32 tile per block ----
        const int wb = bid - NB_CVT - nb_sc;      // 0..63
        const int bn = (wb & 7) * 32;
        const int bk = (wb >> 3) * 32;
        const int tx = t & 31, ty = t >> 5;       // (32, 8)
#pragma unroll
        for (int r = ty; r < 32; r += 8)
            tile[r][tx] = W[(size_t)(bk + r) * FC + bn + tx];
        __syncthreads();
#pragma unroll
        for (int r = ty; r < 32; r += 8)
            g_wh[(size_t)(bn + r) * FC + bk + tx] = __float2half_rn(tile[tx][r]);
    }
}

// =================== mma / cp.async / ldmatrix helpers ===================
__device__ __forceinline__ void mma_f16(float* d, const uint32_t* a, const uint32_t* b) {
    asm volatile(
        "mma.sync.aligned.m16n8k16.row.col.f32.f16.f16.f32 "
        "{%0,%1,%2,%3}, {%4,%5,%6,%7}, {%8,%9}, {%0,%1,%2,%3};"
        : "+f"(d[0]), "+f"(d[1]), "+f"(d[2]), "+f"(d[3])
        : "r"(a[0]), "r"(a[1]), "r"(a[2]), "r"(a[3]),
          "r"(b[0]), "r"(b[1]));
}
__device__ __forceinline__ uint32_t smem_u32(const void* p) {
    uint32_t a;
    asm("{ .reg .u64 t; cvta.to.shared.u64 t, %1; cvt.u32.u64 %0, t; }" : "=r"(a) : "l"(p));
    return a;
}
#define LDSM_X4(r0, r1, r2, r3, addr)                                        \
    asm volatile("ldmatrix.sync.aligned.m8n8.x4.shared.b16 {%0,%1,%2,%3}, [%4];" \
        : "=r"(r0), "=r"(r1), "=r"(r2), "=r"(r3) : "r"(addr))
#define CP_ASYNC16(dst, src) \
    asm volatile("cp.async.cg.shared.global [%0], [%1], 16;" :: "r"(dst), "l"(src))
#define CP_COMMIT() asm volatile("cp.async.commit_group;" ::: "memory")
#define CP_WAIT0()  asm volatile("cp.async.wait_group 0;" ::: "memory")
#define CP_WAIT1()  asm volatile("cp.async.wait_group 1;" ::: "memory")

// =================== kernel 3: xt = xh @ Wh  (BN=256, 512 threads) =========
#define BM 128
#define BN 256
#define BK 64
#define NCH (FC / BK)            // 4
#define A_TILE_B  (128 * 128)    // 16 KB
#define B_TILE_B  (256 * 128)    // 32 KB
#define STAGE_B   (A_TILE_B + B_TILE_B)   // 48 KB
#define A_OFF(p)  ((p) * STAGE_B)
#define B_OFF(p)  ((p) * STAGE_B + A_TILE_B)
#define GEMM_SMEM (2 * STAGE_B)  // 96 KB

__global__ __launch_bounds__(512, 1) void k_gemm() {
    extern __shared__ char sm[];
    const uint32_t sb = smem_u32(sm);

    const int tid  = threadIdx.x;
    const int lane = tid & 31;
    const int wid  = tid >> 5;
    const int wm = (wid & 1) * 64;
    const int wn = (wid >> 1) * 32;
    const int bm = blockIdx.x * BM;

    const int g  = lane >> 2;
    const int tg = lane & 3;

    const int a_lrow  = lane & 15;
    const int a_lchnk = lane >> 4;
    const int b_lrow  = ((lane >> 4) << 3) + (lane & 7);
    const int b_lchnk = (lane >> 3) & 1;

    float acc[4][4][4];
#pragma unroll
    for (int mt = 0; mt < 4; mt++)
#pragma unroll
        for (int nt = 0; nt < 4; nt++)
#pragma unroll
            for (int r = 0; r < 4; r++) acc[mt][nt][r] = 0.0f;

    auto issue = [&](int c, int p) {
        const int k0 = c * BK;
#pragma unroll
        for (int q = 0; q < 2; q++) {      // A: 128 rows x 64 halves
            int id  = q * 512 + tid;
            int row = id >> 3;
            int ch  = id & 7;
            uint32_t dst = sb + A_OFF(p) + row * 128 + ((ch ^ (row & 7)) << 4);
            CP_ASYNC16(dst, &g_xh[(size_t)(bm + row) * FC + k0 + ch * 8]);
        }
#pragma unroll
        for (int q = 0; q < 4; q++) {      // B: 256 rows x 64 halves
            int id  = q * 512 + tid;
            int row = id >> 3;
            int ch  = id & 7;
            uint32_t dst = sb + B_OFF(p) + row * 128 + ((ch ^ (row & 7)) << 4);
            CP_ASYNC16(dst, &g_wh[(size_t)row * FC + k0 + ch * 8]);
        }
        CP_COMMIT();
    };

    issue(0, 0);
    issue(1, 1);

#pragma unroll
    for (int c = 0; c < NCH; c++) {
        const int p = c & 1;
        if (c == NCH - 1) { CP_WAIT0(); } else { CP_WAIT1(); }
        __syncthreads();

        const uint32_t sA = sb + A_OFF(p);
        const uint32_t sB = sb + B_OFF(p);

#pragma unroll
        for (int s = 0; s < 4; s++) {
            uint32_t a[4][4], b[4][2];
#pragma unroll
            for (int mt = 0; mt < 4; mt++) {
                int row = wm + mt * 16 + a_lrow;
                int ch  = (s * 2 + a_lchnk) ^ (row & 7);
                LDSM_X4(a[mt][0], a[mt][1], a[mt][2], a[mt][3],
                        sA + row * 128 + (ch << 4));
            }
#pragma unroll
            for (int pr = 0; pr < 2; pr++) {
                int row = wn + pr * 16 + b_lrow;
                int ch  = (s * 2 + b_lchnk) ^ (row & 7);
                LDSM_X4(b[pr * 2][0], b[pr * 2][1], b[pr * 2 + 1][0], b[pr * 2 + 1][1],
                        sB + row * 128 + (ch << 4));
            }
#pragma unroll
            for (int mt = 0; mt < 4; mt++)
#pragma unroll
                for (int nt = 0; nt < 4; nt++)
                    mma_f16(acc[mt][nt], a[mt], b[nt]);
        }
        __syncthreads();
        if (c + 2 < NCH) issue(c + 2, p);
    }

#pragma unroll
    for (int mt = 0; mt < 4; mt++) {
#pragma unroll
        for (int nt = 0; nt < 4; nt++) {
            int r = bm + wm + mt * 16 + g;
            int c = wn + nt * 8 + tg * 2;
            __half2 h01 = __floats2half2_rn(acc[mt][nt][0], acc[mt][nt][1]);
            __half2 h23 = __floats2half2_rn(acc[mt][nt][2], acc[mt][nt][3]);
            *(__half2*)&g_xt[(size_t)r * FC + c]       = h01;
            *(__half2*)&g_xt[(size_t)(r + 8) * FC + c] = h23;
        }
    }
}

// =================== kernel 4: aggregate (at LTS floor) ===================
// thread t: batch b = t>>5, features f8 = (t&31)*8 (one LDG.128 / neighbor)
__global__ __launch_bounds__(256) void k_aggregate(const float* __restrict__ bias,
                                                   float* __restrict__ out) {
    __shared__ int s_nbr[NN];
    __shared__ int s_off[WORDS];
    __shared__ int s_total;

    const int i = blockIdx.x;
    const int t = threadIdx.x;
    const int b  = t >> 5;
    const int f8 = (t & 31) * 8;

    uint32_t word = (t < WORDS) ? g_adj[i * WORDS + t] : 0u;
    if (t < WORDS) s_off[t] = __popc(word);
    __syncthreads();

    if (t < 32) {   // warp 0: exclusive scan of 128 popcounts
        int v0 = s_off[4 * t], v1 = s_off[4 * t + 1];
        int v2 = s_off[4 * t + 2], v3 = s_off[4 * t + 3];
        int sum = v0 + v1 + v2 + v3;
        int inc = sum;
#pragma unroll
        for (int d = 1; d < 32; d <<= 1) {
            int x = __shfl_up_sync(0xFFFFFFFFu, inc, d);
            if (t >= d) inc += x;
        }
        int exc = inc - sum;
        s_off[4 * t]     = exc;
        s_off[4 * t + 1] = exc + v0;
        s_off[4 * t + 2] = exc + v0 + v1;
        s_off[4 * t + 3] = exc + v0 + v1 + v2;
        if (t == 31) s_total = inc;
    }
    __syncthreads();

    if (t < WORDS) {
        int pos = s_off[t];
        uint32_t m = word;
        while (m) {
            int bit = __ffs(m) - 1;
            m &= m - 1;
            s_nbr[pos++] = t * 32 + bit;
        }
    }
    __syncthreads();

    const int n = s_total;
    const float inv = 1.0f / ((float)n + 1e-6f);
    const __half* __restrict__ xb = g_xt + (size_t)b * NN * FC + f8;

    float a0 = 0.f, a1 = 0.f, a2 = 0.f, a3 = 0.f;
    float a4 = 0.f, a5 = 0.f, a6 = 0.f, a7 = 0.f;

#define ACC8(v)                                               \
    do { const __half2* _h = (const __half2*)&(v); float2 _p; \
        _p = __half22float2(_h[0]); a0 += _p.x; a1 += _p.y;   \
        _p = __half22float2(_h[1]); a2 += _p.x; a3 += _p.y;   \
        _p = __half22float2(_h[2]); a4 += _p.x; a5 += _p.y;   \
        _p = __half22float2(_h[3]); a6 += _p.x; a7 += _p.y; } while (0)

    int k = 0;
    for (; k + 4 <= n; k += 4) {
        uint4 v0 = *(const uint4*)&xb[(size_t)s_nbr[k]     * FC];
        uint4 v1 = *(const uint4*)&xb[(size_t)s_nbr[k + 1] * FC];
        uint4 v2 = *(const uint4*)&xb[(size_t)s_nbr[k + 2] * FC];
        uint4 v3 = *(const uint4*)&xb[(size_t)s_nbr[k + 3] * FC];
        ACC8(v0); ACC8(v1); ACC8(v2); ACC8(v3);
    }
    for (; k < n; k++) {
        uint4 v0 = *(const uint4*)&xb[(size_t)s_nbr[k] * FC];
        ACC8(v0);
    }
#undef ACC8

    float4 bl = *(const float4*)&bias[f8];
    float4 bh = *(const float4*)&bias[f8 + 4];
    float* o = out + ((size_t)b * NN + i) * FC + f8;
    *(float4*)o       = make_float4(a0 * inv + bl.x, a1 * inv + bl.y,
                                    a2 * inv + bl.z, a3 * inv + bl.w);
    *(float4*)(o + 4) = make_float4(a4 * inv + bh.x, a5 * inv + bh.y,
                                    a6 * inv + bh.z, a7 * inv + bh.w);
}

// =================== launch ===================
extern "C" void kernel_launch(void* const* d_in, const int* in_sizes, int n_in,
                              void* d_out, int out_size) {
    const float* x    = (const float*)d_in[0];
    const int*   ei   = (const int*)d_in[1];
    const float* w    = (const float*)d_in[2];
    const float* bias = (const float*)d_in[3];
    float*       out  = (float*)d_out;

    const int E = in_sizes[1] / 2;
    const int M = BB * NN;
    const int nb_sc = E / (256 * 4);          // 128 scatter blocks

    cudaFuncSetAttribute(k_gemm, cudaFuncAttributeMaxDynamicSharedMemorySize,
                         GEMM_SMEM);

    k_clear_adj<<<NN * WORDS / (256 * 8), 256>>>();
    k_front<<<NB_CVT + nb_sc + 64, 256>>>(x, ei, E, nb_sc, w);

    k_gemm<<<M / BM, 512, GEMM_SMEM>>>();

    k_aggregate<<<NN, 256>>>(bias, out);
}

// round 15
// speedup vs baseline: 1.4240x; 1.0423x over previous
#include <cuda_runtime.h>
#include <cuda_fp16.h>
#include <stdint.h>

#define NN 4096
#define FC 256      // F_IN == F_OUT
#define BB 8
#define WORDS (NN / 32)

// ---------------- scratch (no allocations allowed) ----------------
__device__ uint32_t g_adj[NN * WORDS];            // 2 MB bitmask adjacency
__device__ __half   g_xt[(size_t)BB * NN * FC];   // 16 MB: xt = x @ W (fp16)
__device__ __half   g_xh[(size_t)BB * NN * FC];   // 16 MB: x as fp16
__device__ __half   g_wh[FC * FC];                // 128 KB: W^T as fp16 [n][k]

// =================== kernel 1: clear adjacency (tiny) ===================
__global__ __launch_bounds__(256) void k_clear_adj() {
    const int i = (blockIdx.x * 256 + threadIdx.x) * 8;
    *(uint4*)&g_adj[i]     = make_uint4(0u, 0u, 0u, 0u);
    *(uint4*)&g_adj[i + 4] = make_uint4(0u, 0u, 0u, 0u);
}

// =================== kernel 2: fused scatter + wt + cvt ===================
#define NB_CVT 4096
__global__ __launch_bounds__(256) void k_front(const float* __restrict__ x,
                                               const int* __restrict__ ei, int E,
                                               int nb_sc,
                                               const float* __restrict__ W) {
    __shared__ float tile[32][33];
    const int bid = blockIdx.x;
    const int t   = threadIdx.x;

    if (bid < NB_CVT) {
        // ---- cvt: read-once x with streaming hint ----
        const size_t i = ((size_t)bid * 256 + t) * 8;
        float4 v0 = __ldcs((const float4*)&x[i]);
        float4 v1 = __ldcs((const float4*)&x[i + 4]);
        __half2 h0 = __floats2half2_rn(v0.x, v0.y);
        __half2 h1 = __floats2half2_rn(v0.z, v0.w);
        __half2 h2 = __floats2half2_rn(v1.x, v1.y);
        __half2 h3 = __floats2half2_rn(v1.z, v1.w);
        *(uint4*)&g_xh[i] = make_uint4(*(uint32_t*)&h0, *(uint32_t*)&h1,
                                       *(uint32_t*)&h2, *(uint32_t*)&h3);
    } else if (bid < NB_CVT + nb_sc) {
        // ---- scatter: 4 edges/thread ----
        const int e0 = ((bid - NB_CVT) * 256 + t) * 4;
        int s0 = ei[e0], s1 = ei[e0 + 1], s2 = ei[e0 + 2], s3 = ei[e0 + 3];
        int d0 = ei[E + e0], d1 = ei[E + e0 + 1];
        int d2 = ei[E + e0 + 2], d3 = ei[E + e0 + 3];
        atomicOr(&g_adj[s0 * WORDS + (d0 >> 5)], 1u << (d0 & 31));
        atomicOr(&g_adj[s1 * WORDS + (d1 >> 5)], 1u << (d1 & 31));
        atomicOr(&g_adj[s2 * WORDS + (d2 >> 5)], 1u << (d2 & 31));
        atomicOr(&g_adj[s3 * WORDS + (d3 >> 5)], 1u << (d3 & 31));
    } else {
        // ---- wt: W[k][n] -> g_wh[n][k] fp16, 32x32 tile per block ----
        const int wb = bid - NB_CVT - nb_sc;      // 0..63
        const int bn = (wb & 7) * 32;
        const int bk = (wb >> 3) * 32;
        const int tx = t & 31, ty = t >> 5;
#pragma unroll
        for (int r = ty; r < 32; r += 8)
            tile[r][tx] = W[(size_t)(bk + r) * FC + bn + tx];
        __syncthreads();
#pragma unroll
        for (int r = ty; r < 32; r += 8)
            g_wh[(size_t)(bn + r) * FC + bk + tx] = __float2half_rn(tile[tx][r]);
    }
}

// =================== mma / cp.async / ldmatrix helpers ===================
__device__ __forceinline__ void mma_f16(float* d, const uint32_t* a, const uint32_t* b) {
    asm volatile(
        "mma.sync.aligned.m16n8k16.row.col.f32.f16.f16.f32 "
        "{%0,%1,%2,%3}, {%4,%5,%6,%7}, {%8,%9}, {%0,%1,%2,%3};"
        : "+f"(d[0]), "+f"(d[1]), "+f"(d[2]), "+f"(d[3])
        : "r"(a[0]), "r"(a[1]), "r"(a[2]), "r"(a[3]),
          "r"(b[0]), "r"(b[1]));
}
__device__ __forceinline__ uint32_t smem_u32(const void* p) {
    uint32_t a;
    asm("{ .reg .u64 t; cvta.to.shared.u64 t, %1; cvt.u32.u64 %0, t; }" : "=r"(a) : "l"(p));
    return a;
}
#define LDSM_X4(r0, r1, r2, r3, addr)                                        \
    asm volatile("ldmatrix.sync.aligned.m8n8.x4.shared.b16 {%0,%1,%2,%3}, [%4];" \
        : "=r"(r0), "=r"(r1), "=r"(r2), "=r"(r3) : "r"(addr))
#define CP_ASYNC16(dst, src) \
    asm volatile("cp.async.cg.shared.global [%0], [%1], 16;" :: "r"(dst), "l"(src))
#define CP_COMMIT() asm volatile("cp.async.commit_group;" ::: "memory")
#define CP_WAIT0()  asm volatile("cp.async.wait_group 0;" ::: "memory")
#define CP_WAIT1()  asm volatile("cp.async.wait_group 1;" ::: "memory")

// =================== kernel 3: xt = xh @ Wh  (BN=256, 512 threads) =========
#define BM 128
#define BN 256
#define BK 64
#define NCH (FC / BK)            // 4
#define A_TILE_B  (128 * 128)    // 16 KB
#define B_TILE_B  (256 * 128)    // 32 KB
#define STAGE_B   (A_TILE_B + B_TILE_B)   // 48 KB
#define A_OFF(p)  ((p) * STAGE_B)
#define B_OFF(p)  ((p) * STAGE_B + A_TILE_B)
#define GEMM_SMEM (2 * STAGE_B)  // 96 KB

__global__ __launch_bounds__(512, 1) void k_gemm() {
    extern __shared__ char sm[];
    const uint32_t sb = smem_u32(sm);

    const int tid  = threadIdx.x;
    const int lane = tid & 31;
    const int wid  = tid >> 5;
    const int wm = (wid & 1) * 64;
    const int wn = (wid >> 1) * 32;
    const int bm = blockIdx.x * BM;

    const int g  = lane >> 2;
    const int tg = lane & 3;

    const int a_lrow  = lane & 15;
    const int a_lchnk = lane >> 4;
    const int b_lrow  = ((lane >> 4) << 3) + (lane & 7);
    const int b_lchnk = (lane >> 3) & 1;

    float acc[4][4][4];
#pragma unroll
    for (int mt = 0; mt < 4; mt++)
#pragma unroll
        for (int nt = 0; nt < 4; nt++)
#pragma unroll
            for (int r = 0; r < 4; r++) acc[mt][nt][r] = 0.0f;

    auto issue = [&](int c, int p) {
        const int k0 = c * BK;
#pragma unroll
        for (int q = 0; q < 2; q++) {
            int id  = q * 512 + tid;
            int row = id >> 3;
            int ch  = id & 7;
            uint32_t dst = sb + A_OFF(p) + row * 128 + ((ch ^ (row & 7)) << 4);
            CP_ASYNC16(dst, &g_xh[(size_t)(bm + row) * FC + k0 + ch * 8]);
        }
#pragma unroll
        for (int q = 0; q < 4; q++) {
            int id  = q * 512 + tid;
            int row = id >> 3;
            int ch  = id & 7;
            uint32_t dst = sb + B_OFF(p) + row * 128 + ((ch ^ (row & 7)) << 4);
            CP_ASYNC16(dst, &g_wh[(size_t)row * FC + k0 + ch * 8]);
        }
        CP_COMMIT();
    };

    issue(0, 0);
    issue(1, 1);

#pragma unroll
    for (int c = 0; c < NCH; c++) {
        const int p = c & 1;
        if (c == NCH - 1) { CP_WAIT0(); } else { CP_WAIT1(); }
        __syncthreads();

        const uint32_t sA = sb + A_OFF(p);
        const uint32_t sB = sb + B_OFF(p);

#pragma unroll
        for (int s = 0; s < 4; s++) {
            uint32_t a[4][4], b[4][2];
#pragma unroll
            for (int mt = 0; mt < 4; mt++) {
                int row = wm + mt * 16 + a_lrow;
                int ch  = (s * 2 + a_lchnk) ^ (row & 7);
                LDSM_X4(a[mt][0], a[mt][1], a[mt][2], a[mt][3],
                        sA + row * 128 + (ch << 4));
            }
#pragma unroll
            for (int pr = 0; pr < 2; pr++) {
                int row = wn + pr * 16 + b_lrow;
                int ch  = (s * 2 + b_lchnk) ^ (row & 7);
                LDSM_X4(b[pr * 2][0], b[pr * 2][1], b[pr * 2 + 1][0], b[pr * 2 + 1][1],
                        sB + row * 128 + (ch << 4));
            }
#pragma unroll
            for (int mt = 0; mt < 4; mt++)
#pragma unroll
                for (int nt = 0; nt < 4; nt++)
                    mma_f16(acc[mt][nt], a[mt], b[nt]);
        }
        __syncthreads();
        if (c + 2 < NCH) issue(c + 2, p);
    }

#pragma unroll
    for (int mt = 0; mt < 4; mt++) {
#pragma unroll
        for (int nt = 0; nt < 4; nt++) {
            int r = bm + wm + mt * 16 + g;
            int c = wn + nt * 8 + tg * 2;
            __half2 h01 = __floats2half2_rn(acc[mt][nt][0], acc[mt][nt][1]);
            __half2 h23 = __floats2half2_rn(acc[mt][nt][2], acc[mt][nt][3]);
            *(__half2*)&g_xt[(size_t)r * FC + c]       = h01;
            *(__half2*)&g_xt[(size_t)(r + 8) * FC + c] = h23;
        }
    }
}

// =================== kernel 4: aggregate (HADD2 pairing) ===================
// thread t: batch b = t>>5, features f8 = (t&31)*8 (one LDG.128 / neighbor)
__global__ __launch_bounds__(256) void k_aggregate(const float* __restrict__ bias,
                                                   float* __restrict__ out) {
    __shared__ int s_nbr[NN];    // neighbor index premultiplied by FC
    __shared__ int s_off[WORDS];
    __shared__ int s_total;

    const int i = blockIdx.x;
    const int t = threadIdx.x;
    const int b  = t >> 5;
    const int f8 = (t & 31) * 8;

    uint32_t word = (t < WORDS) ? g_adj[i * WORDS + t] : 0u;
    if (t < WORDS) s_off[t] = __popc(word);
    __syncthreads();

    if (t < 32) {   // warp 0: exclusive scan of 128 popcounts
        int v0 = s_off[4 * t], v1 = s_off[4 * t + 1];
        int v2 = s_off[4 * t + 2], v3 = s_off[4 * t + 3];
        int sum = v0 + v1 + v2 + v3;
        int inc = sum;
#pragma unroll
        for (int d = 1; d < 32; d <<= 1) {
            int x = __shfl_up_sync(0xFFFFFFFFu, inc, d);
            if (t >= d) inc += x;
        }
        int exc = inc - sum;
        s_off[4 * t]     = exc;
        s_off[4 * t + 1] = exc + v0;
        s_off[4 * t + 2] = exc + v0 + v1;
        s_off[4 * t + 3] = exc + v0 + v1 + v2;
        if (t == 31) s_total = inc;
    }
    __syncthreads();

    if (t < WORDS) {
        int pos = s_off[t];
        uint32_t m = word;
        while (m) {
            int bit = __ffs(m) - 1;
            m &= m - 1;
            s_nbr[pos++] = (t * 32 + bit) * FC;   // premultiplied offset
        }
    }
    __syncthreads();

    const int n = s_total;
    const float inv = 1.0f / ((float)n + 1e-6f);
    const __half* __restrict__ xb = g_xt + (size_t)b * NN * FC + f8;

    float a0 = 0.f, a1 = 0.f, a2 = 0.f, a3 = 0.f;
    float a4 = 0.f, a5 = 0.f, a6 = 0.f, a7 = 0.f;

    // fp32 accumulate a full half2x4 vector (exact path, used for tails)
#define ACC8(v)                                               \
    do { const __half2* _h = (const __half2*)&(v); float2 _p; \
        _p = __half22float2(_h[0]); a0 += _p.x; a1 += _p.y;   \
        _p = __half22float2(_h[1]); a2 += _p.x; a3 += _p.y;   \
        _p = __half22float2(_h[2]); a4 += _p.x; a5 += _p.y;   \
        _p = __half22float2(_h[3]); a6 += _p.x; a7 += _p.y; } while (0)
    // pair two neighbor vectors in fp16, then fp32-accumulate the pair sum
#define ACCPAIR(va, vb)                                           \
    do { const __half2* _ha = (const __half2*)&(va);              \
         const __half2* _hb = (const __half2*)&(vb); float2 _p;   \
        _p = __half22float2(__hadd2(_ha[0], _hb[0])); a0 += _p.x; a1 += _p.y; \
        _p = __half22float2(__hadd2(_ha[1], _hb[1])); a2 += _p.x; a3 += _p.y; \
        _p = __half22float2(__hadd2(_ha[2], _hb[2])); a4 += _p.x; a5 += _p.y; \
        _p = __half22float2(__hadd2(_ha[3], _hb[3])); a6 += _p.x; a7 += _p.y; } while (0)

    int k = 0;
    for (; k + 4 <= n; k += 4) {
        uint4 v0 = *(const uint4*)&xb[s_nbr[k]];
        uint4 v1 = *(const uint4*)&xb[s_nbr[k + 1]];
        uint4 v2 = *(const uint4*)&xb[s_nbr[k + 2]];
        uint4 v3 = *(const uint4*)&xb[s_nbr[k + 3]];
        ACCPAIR(v0, v1);
        ACCPAIR(v2, v3);
    }
    if (k + 2 <= n) {
        uint4 v0 = *(const uint4*)&xb[s_nbr[k]];
        uint4 v1 = *(const uint4*)&xb[s_nbr[k + 1]];
        ACCPAIR(v0, v1);
        k += 2;
    }
    if (k < n) {
        uint4 v0 = *(const uint4*)&xb[s_nbr[k]];
        ACC8(v0);
    }
#undef ACC8
#undef ACCPAIR

    float4 bl = *(const float4*)&bias[f8];
    float4 bh = *(const float4*)&bias[f8 + 4];
    float* o = out + ((size_t)b * NN + i) * FC + f8;
    *(float4*)o       = make_float4(a0 * inv + bl.x, a1 * inv + bl.y,
                                    a2 * inv + bl.z, a3 * inv + bl.w);
    *(float4*)(o + 4) = make_float4(a4 * inv + bh.x, a5 * inv + bh.y,
                                    a6 * inv + bh.z, a7 * inv + bh.w);
}

// =================== launch ===================
extern "C" void kernel_launch(void* const* d_in, const int* in_sizes, int n_in,
                              void* d_out, int out_size) {
    const float* x    = (const float*)d_in[0];
    const int*   ei   = (const int*)d_in[1];
    const float* w    = (const float*)d_in[2];
    const float* bias = (const float*)d_in[3];
    float*       out  = (float*)d_out;

    const int E = in_sizes[1] / 2;
    const int M = BB * NN;
    const int nb_sc = E / (256 * 4);          // 128 scatter blocks

    cudaFuncSetAttribute(k_gemm, cudaFuncAttributeMaxDynamicSharedMemorySize,
                         GEMM_SMEM);

    k_clear_adj<<<NN * WORDS / (256 * 8), 256>>>();
    k_front<<<NB_CVT + nb_sc + 64, 256>>>(x, ei, E, nb_sc, w);

    k_gemm<<<M / BM, 512, GEMM_SMEM>>>();

    k_aggregate<<<NN, 256>>>(bias, out);
}

// round 16
// speedup vs baseline: 1.4248x; 1.0005x over previous
#include <cuda_runtime.h>
#include <cuda_fp16.h>
#include <stdint.h>

#define NN 4096
#define FC 256      // F_IN == F_OUT
#define BB 8
#define WORDS (NN / 32)

// ---------------- scratch (no allocations allowed) ----------------
__device__ uint32_t g_adj[NN * WORDS];            // 2 MB bitmask adjacency
__device__ __half   g_xt[(size_t)BB * NN * FC];   // 16 MB: xt = x @ W (fp16)
__device__ __half   g_xh[(size_t)BB * NN * FC];   // 16 MB: x as fp16
__device__ __half   g_wh[FC * FC];                // 128 KB: W^T as fp16 [n][k]

// =================== kernel 1: clear adjacency (tiny) ===================
__global__ __launch_bounds__(256) void k_clear_adj() {
    const int i = (blockIdx.x * 256 + threadIdx.x) * 8;
    *(uint4*)&g_adj[i]     = make_uint4(0u, 0u, 0u, 0u);
    *(uint4*)&g_adj[i + 4] = make_uint4(0u, 0u, 0u, 0u);
}

// =================== kernel 2: fused scatter + wt + cvt ===================
#define NB_CVT 4096
__global__ __launch_bounds__(256) void k_front(const float* __restrict__ x,
                                               const int* __restrict__ ei, int E,
                                               int nb_sc,
                                               const float* __restrict__ W) {
    __shared__ float tile[32][33];
    const int bid = blockIdx.x;
    const int t   = threadIdx.x;

    if (bid < NB_CVT) {
        // ---- cvt: read-once x with streaming hint ----
        const size_t i = ((size_t)bid * 256 + t) * 8;
        float4 v0 = __ldcs((const float4*)&x[i]);
        float4 v1 = __ldcs((const float4*)&x[i + 4]);
        __half2 h0 = __floats2half2_rn(v0.x, v0.y);
        __half2 h1 = __floats2half2_rn(v0.z, v0.w);
        __half2 h2 = __floats2half2_rn(v1.x, v1.y);
        __half2 h3 = __floats2half2_rn(v1.z, v1.w);
        *(uint4*)&g_xh[i] = make_uint4(*(uint32_t*)&h0, *(uint32_t*)&h1,
                                       *(uint32_t*)&h2, *(uint32_t*)&h3);
    } else if (bid < NB_CVT + nb_sc) {
        // ---- scatter: 4 edges/thread ----
        const int e0 = ((bid - NB_CVT) * 256 + t) * 4;
        int s0 = ei[e0], s1 = ei[e0 + 1], s2 = ei[e0 + 2], s3 = ei[e0 + 3];
        int d0 = ei[E + e0], d1 = ei[E + e0 + 1];
        int d2 = ei[E + e0 + 2], d3 = ei[E + e0 + 3];
        atomicOr(&g_adj[s0 * WORDS + (d0 >> 5)], 1u << (d0 & 31));
        atomicOr(&g_adj[s1 * WORDS + (d1 >> 5)], 1u << (d1 & 31));
        atomicOr(&g_adj[s2 * WORDS + (d2 >> 5)], 1u << (d2 & 31));
        atomicOr(&g_adj[s3 * WORDS + (d3 >> 5)], 1u << (d3 & 31));
    } else {
        // ---- wt: W[k][n] -> g_wh[n][k] fp16, 32x32 tile per block ----
        const int wb = bid - NB_CVT - nb_sc;      // 0..63
        const int bn = (wb & 7) * 32;
        const int bk = (wb >> 3) * 32;
        const int tx = t & 31, ty = t >> 5;
#pragma unroll
        for (int r = ty; r < 32; r += 8)
            tile[r][tx] = W[(size_t)(bk + r) * FC + bn + tx];
        __syncthreads();
#pragma unroll
        for (int r = ty; r < 32; r += 8)
            g_wh[(size_t)(bn + r) * FC + bk + tx] = __float2half_rn(tile[tx][r]);
    }
}

// =================== mma / cp.async / ldmatrix helpers ===================
__device__ __forceinline__ void mma_f16(float* d, const uint32_t* a, const uint32_t* b) {
    asm volatile(
        "mma.sync.aligned.m16n8k16.row.col.f32.f16.f16.f32 "
        "{%0,%1,%2,%3}, {%4,%5,%6,%7}, {%8,%9}, {%0,%1,%2,%3};"
        : "+f"(d[0]), "+f"(d[1]), "+f"(d[2]), "+f"(d[3])
        : "r"(a[0]), "r"(a[1]), "r"(a[2]), "r"(a[3]),
          "r"(b[0]), "r"(b[1]));
}
__device__ __forceinline__ uint32_t smem_u32(const void* p) {
    uint32_t a;
    asm("{ .reg .u64 t; cvta.to.shared.u64 t, %1; cvt.u32.u64 %0, t; }" : "=r"(a) : "l"(p));
    return a;
}
#define LDSM_X4(r0, r1, r2, r3, addr)                                        \
    asm volatile("ldmatrix.sync.aligned.m8n8.x4.shared.b16 {%0,%1,%2,%3}, [%4];" \
        : "=r"(r0), "=r"(r1), "=r"(r2), "=r"(r3) : "r"(addr))
#define CP_ASYNC16(dst, src) \
    asm volatile("cp.async.cg.shared.global [%0], [%1], 16;" :: "r"(dst), "l"(src))
#define CP_COMMIT() asm volatile("cp.async.commit_group;" ::: "memory")
#define CP_WAIT0()  asm volatile("cp.async.wait_group 0;" ::: "memory")
#define CP_WAIT1()  asm volatile("cp.async.wait_group 1;" ::: "memory")

// =================== kernel 3: xt = xh @ Wh  (BN=256, 512 threads) =========
#define BM 128
#define BN 256
#define BK 64
#define NCH (FC / BK)            // 4
#define A_TILE_B  (128 * 128)    // 16 KB
#define B_TILE_B  (256 * 128)    // 32 KB
#define STAGE_B   (A_TILE_B + B_TILE_B)   // 48 KB
#define A_OFF(p)  ((p) * STAGE_B)
#define B_OFF(p)  ((p) * STAGE_B + A_TILE_B)
#define GEMM_SMEM (2 * STAGE_B)  // 96 KB

__global__ __launch_bounds__(512, 1) void k_gemm() {
    extern __shared__ char sm[];
    const uint32_t sb = smem_u32(sm);

    const int tid  = threadIdx.x;
    const int lane = tid & 31;
    const int wid  = tid >> 5;
    const int wm = (wid & 1) * 64;
    const int wn = (wid >> 1) * 32;
    const int bm = blockIdx.x * BM;

    const int g  = lane >> 2;
    const int tg = lane & 3;

    const int a_lrow  = lane & 15;
    const int a_lchnk = lane >> 4;
    const int b_lrow  = ((lane >> 4) << 3) + (lane & 7);
    const int b_lchnk = (lane >> 3) & 1;

    float acc[4][4][4];
#pragma unroll
    for (int mt = 0; mt < 4; mt++)
#pragma unroll
        for (int nt = 0; nt < 4; nt++)
#pragma unroll
            for (int r = 0; r < 4; r++) acc[mt][nt][r] = 0.0f;

    auto issue = [&](int c, int p) {
        const int k0 = c * BK;
#pragma unroll
        for (int q = 0; q < 2; q++) {
            int id  = q * 512 + tid;
            int row = id >> 3;
            int ch  = id & 7;
            uint32_t dst = sb + A_OFF(p) + row * 128 + ((ch ^ (row & 7)) << 4);
            CP_ASYNC16(dst, &g_xh[(size_t)(bm + row) * FC + k0 + ch * 8]);
        }
#pragma unroll
        for (int q = 0; q < 4; q++) {
            int id  = q * 512 + tid;
            int row = id >> 3;
            int ch  = id & 7;
            uint32_t dst = sb + B_OFF(p) + row * 128 + ((ch ^ (row & 7)) << 4);
            CP_ASYNC16(dst, &g_wh[(size_t)row * FC + k0 + ch * 8]);
        }
        CP_COMMIT();
    };

    issue(0, 0);
    issue(1, 1);

#pragma unroll
    for (int c = 0; c < NCH; c++) {
        const int p = c & 1;
        if (c == NCH - 1) { CP_WAIT0(); } else { CP_WAIT1(); }
        __syncthreads();

        const uint32_t sA = sb + A_OFF(p);
        const uint32_t sB = sb + B_OFF(p);

#pragma unroll
        for (int s = 0; s < 4; s++) {
            uint32_t a[4][4], b[4][2];
#pragma unroll
            for (int mt = 0; mt < 4; mt++) {
                int row = wm + mt * 16 + a_lrow;
                int ch  = (s * 2 + a_lchnk) ^ (row & 7);
                LDSM_X4(a[mt][0], a[mt][1], a[mt][2], a[mt][3],
                        sA + row * 128 + (ch << 4));
            }
#pragma unroll
            for (int pr = 0; pr < 2; pr++) {
                int row = wn + pr * 16 + b_lrow;
                int ch  = (s * 2 + b_lchnk) ^ (row & 7);
                LDSM_X4(b[pr * 2][0], b[pr * 2][1], b[pr * 2 + 1][0], b[pr * 2 + 1][1],
                        sB + row * 128 + (ch << 4));
            }
#pragma unroll
            for (int mt = 0; mt < 4; mt++)
#pragma unroll
                for (int nt = 0; nt < 4; nt++)
                    mma_f16(acc[mt][nt], a[mt], b[nt]);
        }
        __syncthreads();
        if (c + 2 < NCH) issue(c + 2, p);
    }

#pragma unroll
    for (int mt = 0; mt < 4; mt++) {
#pragma unroll
        for (int nt = 0; nt < 4; nt++) {
            int r = bm + wm + mt * 16 + g;
            int c = wn + nt * 8 + tg * 2;
            __half2 h01 = __floats2half2_rn(acc[mt][nt][0], acc[mt][nt][1]);
            __half2 h23 = __floats2half2_rn(acc[mt][nt][2], acc[mt][nt][3]);
            *(__half2*)&g_xt[(size_t)r * FC + c]       = h01;
            *(__half2*)&g_xt[(size_t)(r + 8) * FC + c] = h23;
        }
    }
}

// =================== kernel 4: aggregate (4-way fp16 tree) ===================
// thread t: batch b = t>>5, features f8 = (t&31)*8 (one LDG.128 / neighbor)
__global__ __launch_bounds__(256) void k_aggregate(const float* __restrict__ bias,
                                                   float* __restrict__ out) {
    __shared__ int s_nbr[NN];    // neighbor index premultiplied by FC
    __shared__ int s_off[WORDS];
    __shared__ int s_total;

    const int i = blockIdx.x;
    const int t = threadIdx.x;
    const int b  = t >> 5;
    const int f8 = (t & 31) * 8;

    uint32_t word = (t < WORDS) ? g_adj[i * WORDS + t] : 0u;
    if (t < WORDS) s_off[t] = __popc(word);
    __syncthreads();

    if (t < 32) {   // warp 0: exclusive scan of 128 popcounts
        int v0 = s_off[4 * t], v1 = s_off[4 * t + 1];
        int v2 = s_off[4 * t + 2], v3 = s_off[4 * t + 3];
        int sum = v0 + v1 + v2 + v3;
        int inc = sum;
#pragma unroll
        for (int d = 1; d < 32; d <<= 1) {
            int x = __shfl_up_sync(0xFFFFFFFFu, inc, d);
            if (t >= d) inc += x;
        }
        int exc = inc - sum;
        s_off[4 * t]     = exc;
        s_off[4 * t + 1] = exc + v0;
        s_off[4 * t + 2] = exc + v0 + v1;
        s_off[4 * t + 3] = exc + v0 + v1 + v2;
        if (t == 31) s_total = inc;
    }
    __syncthreads();

    if (t < WORDS) {
        int pos = s_off[t];
        uint32_t m = word;
        while (m) {
            int bit = __ffs(m) - 1;
            m &= m - 1;
            s_nbr[pos++] = (t * 32 + bit) * FC;   // premultiplied offset
        }
    }
    __syncthreads();

    const int n = s_total;
    const float inv = 1.0f / ((float)n + 1e-6f);
    const __half* __restrict__ xb = g_xt + (size_t)b * NN * FC + f8;

    float a0 = 0.f, a1 = 0.f, a2 = 0.f, a3 = 0.f;
    float a4 = 0.f, a5 = 0.f, a6 = 0.f, a7 = 0.f;

    // exact fp32 accumulate of one vector (tail)
#define ACC8(v)                                               \
    do { const __half2* _h = (const __half2*)&(v); float2 _p; \
        _p = __half22float2(_h[0]); a0 += _p.x; a1 += _p.y;   \
        _p = __half22float2(_h[1]); a2 += _p.x; a3 += _p.y;   \
        _p = __half22float2(_h[2]); a4 += _p.x; a5 += _p.y;   \
        _p = __half22float2(_h[3]); a6 += _p.x; a7 += _p.y; } while (0)
    // level-1 pair (tail of 2-3)
#define ACCPAIR(va, vb)                                           \
    do { const __half2* _ha = (const __half2*)&(va);              \
         const __half2* _hb = (const __half2*)&(vb); float2 _p;   \
        _p = __half22float2(__hadd2(_ha[0], _hb[0])); a0 += _p.x; a1 += _p.y; \
        _p = __half22float2(__hadd2(_ha[1], _hb[1])); a2 += _p.x; a3 += _p.y; \
        _p = __half22float2(__hadd2(_ha[2], _hb[2])); a4 += _p.x; a5 += _p.y; \
        _p = __half22float2(__hadd2(_ha[3], _hb[3])); a6 += _p.x; a7 += _p.y; } while (0)
    // 4-way fp16 tree: (v0+v1)+(v2+v3) in fp16, single fp32 accumulate
#define ACCQUAD(v0_, v1_, v2_, v3_)                               \
    do { const __half2* _h0 = (const __half2*)&(v0_);             \
         const __half2* _h1 = (const __half2*)&(v1_);             \
         const __half2* _h2 = (const __half2*)&(v2_);             \
         const __half2* _h3 = (const __half2*)&(v3_); float2 _p;  \
        _p = __half22float2(__hadd2(__hadd2(_h0[0], _h1[0]),      \
                                    __hadd2(_h2[0], _h3[0])));    \
        a0 += _p.x; a1 += _p.y;                                   \
        _p = __half22float2(__hadd2(__hadd2(_h0[1], _h1[1]),      \
                                    __hadd2(_h2[1], _h3[1])));    \
        a2 += _p.x; a3 += _p.y;                                   \
        _p = __half22float2(__hadd2(__hadd2(_h0[2], _h1[2]),      \
                                    __hadd2(_h2[2], _h3[2])));    \
        a4 += _p.x; a5 += _p.y;                                   \
        _p = __half22float2(__hadd2(__hadd2(_h0[3], _h1[3]),      \
                                    __hadd2(_h2[3], _h3[3])));    \
        a6 += _p.x; a7 += _p.y; } while (0)

    int k = 0;
    for (; k + 4 <= n; k += 4) {
        uint4 v0 = *(const uint4*)&xb[s_nbr[k]];
        uint4 v1 = *(const uint4*)&xb[s_nbr[k + 1]];
        uint4 v2 = *(const uint4*)&xb[s_nbr[k + 2]];
        uint4 v3 = *(const uint4*)&xb[s_nbr[k + 3]];
        ACCQUAD(v0, v1, v2, v3);
    }
    if (k + 2 <= n) {
        uint4 v0 = *(const uint4*)&xb[s_nbr[k]];
        uint4 v1 = *(const uint4*)&xb[s_nbr[k + 1]];
        ACCPAIR(v0, v1);
        k += 2;
    }
    if (k < n) {
        uint4 v0 = *(const uint4*)&xb[s_nbr[k]];
        ACC8(v0);
    }
#undef ACC8
#undef ACCPAIR
#undef ACCQUAD

    float4 bl = *(const float4*)&bias[f8];
    float4 bh = *(const float4*)&bias[f8 + 4];
    float* o = out + ((size_t)b * NN + i) * FC + f8;
    *(float4*)o       = make_float4(a0 * inv + bl.x, a1 * inv + bl.y,
                                    a2 * inv + bl.z, a3 * inv + bl.w);
    *(float4*)(o + 4) = make_float4(a4 * inv + bh.x, a5 * inv + bh.y,
                                    a6 * inv + bh.z, a7 * inv + bh.w);
}

// =================== launch ===================
extern "C" void kernel_launch(void* const* d_in, const int* in_sizes, int n_in,
                              void* d_out, int out_size) {
    const float* x    = (const float*)d_in[0];
    const int*   ei   = (const int*)d_in[1];
    const float* w    = (const float*)d_in[2];
    const float* bias = (const float*)d_in[3];
    float*       out  = (float*)d_out;

    const int E = in_sizes[1] / 2;
    const int M = BB * NN;
    const int nb_sc = E / (256 * 4);          // 128 scatter blocks

    cudaFuncSetAttribute(k_gemm, cudaFuncAttributeMaxDynamicSharedMemorySize,
                         GEMM_SMEM);

    k_clear_adj<<<NN * WORDS / (256 * 8), 256>>>();
    k_front<<<NB_CVT + nb_sc + 64, 256>>>(x, ei, E, nb_sc, w);

    k_gemm<<<M / BM, 512, GEMM_SMEM>>>();

    k_aggregate<<<NN, 256>>>(bias, out);
}

// round 17
// speedup vs baseline: 1.4623x; 1.0263x over previous
#include <cuda_runtime.h>
#include <cuda_fp16.h>
#include <stdint.h>

#define NN 4096
#define FC 256      // F_IN == F_OUT
#define BB 8
#define WORDS (NN / 32)

// ---------------- scratch (no allocations allowed) ----------------
__device__ uint32_t g_adj[NN * WORDS];            // 2 MB bitmask adjacency
__device__ __half   g_xt[(size_t)BB * NN * FC];   // 16 MB: xt = x @ W (fp16)
__device__ __half   g_xh[(size_t)BB * NN * FC];   // 16 MB: x as fp16
__device__ __half   g_wh[FC * FC];                // 128 KB: W^T as fp16 [n][k]

// =================== kernel 1: clear adjacency (tiny) ===================
__global__ __launch_bounds__(256) void k_clear_adj() {
    const int i = (blockIdx.x * 256 + threadIdx.x) * 8;
    *(uint4*)&g_adj[i]     = make_uint4(0u, 0u, 0u, 0u);
    *(uint4*)&g_adj[i + 4] = make_uint4(0u, 0u, 0u, 0u);
}

// =================== kernel 2: fused scatter + wt + cvt ===================
#define NB_CVT 4096
__global__ __launch_bounds__(256) void k_front(const float* __restrict__ x,
                                               const int* __restrict__ ei, int E,
                                               int nb_sc,
                                               const float* __restrict__ W) {
    __shared__ float tile[32][33];
    const int bid = blockIdx.x;
    const int t   = threadIdx.x;

    if (bid < NB_CVT) {
        // ---- cvt: read-once x with streaming hint ----
        const size_t i = ((size_t)bid * 256 + t) * 8;
        float4 v0 = __ldcs((const float4*)&x[i]);
        float4 v1 = __ldcs((const float4*)&x[i + 4]);
        __half2 h0 = __floats2half2_rn(v0.x, v0.y);
        __half2 h1 = __floats2half2_rn(v0.z, v0.w);
        __half2 h2 = __floats2half2_rn(v1.x, v1.y);
        __half2 h3 = __floats2half2_rn(v1.z, v1.w);
        *(uint4*)&g_xh[i] = make_uint4(*(uint32_t*)&h0, *(uint32_t*)&h1,
                                       *(uint32_t*)&h2, *(uint32_t*)&h3);
    } else if (bid < NB_CVT + nb_sc) {
        // ---- scatter: 4 edges/thread ----
        const int e0 = ((bid - NB_CVT) * 256 + t) * 4;
        int s0 = ei[e0], s1 = ei[e0 + 1], s2 = ei[e0 + 2], s3 = ei[e0 + 3];
        int d0 = ei[E + e0], d1 = ei[E + e0 + 1];
        int d2 = ei[E + e0 + 2], d3 = ei[E + e0 + 3];
        atomicOr(&g_adj[s0 * WORDS + (d0 >> 5)], 1u << (d0 & 31));
        atomicOr(&g_adj[s1 * WORDS + (d1 >> 5)], 1u << (d1 & 31));
        atomicOr(&g_adj[s2 * WORDS + (d2 >> 5)], 1u << (d2 & 31));
        atomicOr(&g_adj[s3 * WORDS + (d3 >> 5)], 1u << (d3 & 31));
    } else {
        // ---- wt: W[k][n] -> g_wh[n][k] fp16, 32x32 tile per block ----
        const int wb = bid - NB_CVT - nb_sc;      // 0..63
        const int bn = (wb & 7) * 32;
        const int bk = (wb >> 3) * 32;
        const int tx = t & 31, ty = t >> 5;
#pragma unroll
        for (int r = ty; r < 32; r += 8)
            tile[r][tx] = W[(size_t)(bk + r) * FC + bn + tx];
        __syncthreads();
#pragma unroll
        for (int r = ty; r < 32; r += 8)
            g_wh[(size_t)(bn + r) * FC + bk + tx] = __float2half_rn(tile[tx][r]);
    }
}

// =================== mma / cp.async / ldmatrix helpers ===================
__device__ __forceinline__ void mma_f16(float* d, const uint32_t* a, const uint32_t* b) {
    asm volatile(
        "mma.sync.aligned.m16n8k16.row.col.f32.f16.f16.f32 "
        "{%0,%1,%2,%3}, {%4,%5,%6,%7}, {%8,%9}, {%0,%1,%2,%3};"
        : "+f"(d[0]), "+f"(d[1]), "+f"(d[2]), "+f"(d[3])
        : "r"(a[0]), "r"(a[1]), "r"(a[2]), "r"(a[3]),
          "r"(b[0]), "r"(b[1]));
}
__device__ __forceinline__ uint32_t smem_u32(const void* p) {
    uint32_t a;
    asm("{ .reg .u64 t; cvta.to.shared.u64 t, %1; cvt.u32.u64 %0, t; }" : "=r"(a) : "l"(p));
    return a;
}
#define LDSM_X4(r0, r1, r2, r3, addr)                                        \
    asm volatile("ldmatrix.sync.aligned.m8n8.x4.shared.b16 {%0,%1,%2,%3}, [%4];" \
        : "=r"(r0), "=r"(r1), "=r"(r2), "=r"(r3) : "r"(addr))
#define CP_ASYNC16(dst, src) \
    asm volatile("cp.async.cg.shared.global [%0], [%1], 16;" :: "r"(dst), "l"(src))
#define CP_COMMIT() asm volatile("cp.async.commit_group;" ::: "memory")
#define CP_WAITN(n) asm volatile("cp.async.wait_group %0;" :: "n"(n) : "memory")

// =================== kernel 3: xt = xh @ Wh  (BN=256, 3-stage) =============
#define BM 128
#define BN 256
#define BK 64
#define NCH (FC / BK)            // 4
#define A_TILE_B  (128 * 128)    // 16 KB
#define B_TILE_B  (256 * 128)    // 32 KB
#define STAGE_B   (A_TILE_B + B_TILE_B)   // 48 KB
#define A_OFF(p)  ((p) * STAGE_B)
#define B_OFF(p)  ((p) * STAGE_B + A_TILE_B)
#define GEMM_SMEM (3 * STAGE_B)  // 144 KB, 1 CTA/SM

__global__ __launch_bounds__(512, 1) void k_gemm() {
    extern __shared__ char sm[];
    const uint32_t sb = smem_u32(sm);

    const int tid  = threadIdx.x;
    const int lane = tid & 31;
    const int wid  = tid >> 5;
    const int wm = (wid & 1) * 64;
    const int wn = (wid >> 1) * 32;
    const int bm = blockIdx.x * BM;

    const int g  = lane >> 2;
    const int tg = lane & 3;

    const int a_lrow  = lane & 15;
    const int a_lchnk = lane >> 4;
    const int b_lrow  = ((lane >> 4) << 3) + (lane & 7);
    const int b_lchnk = (lane >> 3) & 1;

    float acc[4][4][4];
#pragma unroll
    for (int mt = 0; mt < 4; mt++)
#pragma unroll
        for (int nt = 0; nt < 4; nt++)
#pragma unroll
            for (int r = 0; r < 4; r++) acc[mt][nt][r] = 0.0f;

    auto issue = [&](int c, int p) {
        const int k0 = c * BK;
#pragma unroll
        for (int q = 0; q < 2; q++) {
            int id  = q * 512 + tid;
            int row = id >> 3;
            int ch  = id & 7;
            uint32_t dst = sb + A_OFF(p) + row * 128 + ((ch ^ (row & 7)) << 4);
            CP_ASYNC16(dst, &g_xh[(size_t)(bm + row) * FC + k0 + ch * 8]);
        }
#pragma unroll
        for (int q = 0; q < 4; q++) {
            int id  = q * 512 + tid;
            int row = id >> 3;
            int ch  = id & 7;
            uint32_t dst = sb + B_OFF(p) + row * 128 + ((ch ^ (row & 7)) << 4);
            CP_ASYNC16(dst, &g_wh[(size_t)row * FC + k0 + ch * 8]);
        }
        CP_COMMIT();
    };

    issue(0, 0);
    issue(1, 1);

#pragma unroll
    for (int c = 0; c < NCH; c++) {
        const int p = c % 3;
        if (c == NCH - 1) { CP_WAITN(0); } else { CP_WAITN(1); }
        __syncthreads();            // chunk c visible; compute(c-1) done -> stage (c+2)%3 free

        if (c + 2 < NCH) issue(c + 2, (c + 2) % 3);   // prefetch during compute

        const uint32_t sA = sb + A_OFF(p);
        const uint32_t sB = sb + B_OFF(p);

#pragma unroll
        for (int s = 0; s < 4; s++) {
            uint32_t a[4][4], b[4][2];
#pragma unroll
            for (int mt = 0; mt < 4; mt++) {
                int row = wm + mt * 16 + a_lrow;
                int ch  = (s * 2 + a_lchnk) ^ (row & 7);
                LDSM_X4(a[mt][0], a[mt][1], a[mt][2], a[mt][3],
                        sA + row * 128 + (ch << 4));
            }
#pragma unroll
            for (int pr = 0; pr < 2; pr++) {
                int row = wn + pr * 16 + b_lrow;
                int ch  = (s * 2 + b_lchnk) ^ (row & 7);
                LDSM_X4(b[pr * 2][0], b[pr * 2][1], b[pr * 2 + 1][0], b[pr * 2 + 1][1],
                        sB + row * 128 + (ch << 4));
            }
#pragma unroll
            for (int mt = 0; mt < 4; mt++)
#pragma unroll
                for (int nt = 0; nt < 4; nt++)
                    mma_f16(acc[mt][nt], a[mt], b[nt]);
        }
        // single sync per iteration (top of next iter)
    }

#pragma unroll
    for (int mt = 0; mt < 4; mt++) {
#pragma unroll
        for (int nt = 0; nt < 4; nt++) {
            int r = bm + wm + mt * 16 + g;
            int c = wn + nt * 8 + tg * 2;
            __half2 h01 = __floats2half2_rn(acc[mt][nt][0], acc[mt][nt][1]);
            __half2 h23 = __floats2half2_rn(acc[mt][nt][2], acc[mt][nt][3]);
            *(__half2*)&g_xt[(size_t)r * FC + c]       = h01;
            *(__half2*)&g_xt[(size_t)(r + 8) * FC + c] = h23;
        }
    }
}

// =================== kernel 4: aggregate (R15 pair version, 32 regs) ========
// thread t: batch b = t>>5, features f8 = (t&31)*8 (one LDG.128 / neighbor)
__global__ __launch_bounds__(256) void k_aggregate(const float* __restrict__ bias,
                                                   float* __restrict__ out) {
    __shared__ int s_nbr[NN];    // neighbor index premultiplied by FC
    __shared__ int s_off[WORDS];
    __shared__ int s_total;

    const int i = blockIdx.x;
    const int t = threadIdx.x;
    const int b  = t >> 5;
    const int f8 = (t & 31) * 8;

    uint32_t word = (t < WORDS) ? g_adj[i * WORDS + t] : 0u;
    if (t < WORDS) s_off[t] = __popc(word);
    __syncthreads();

    if (t < 32) {   // warp 0: exclusive scan of 128 popcounts
        int v0 = s_off[4 * t], v1 = s_off[4 * t + 1];
        int v2 = s_off[4 * t + 2], v3 = s_off[4 * t + 3];
        int sum = v0 + v1 + v2 + v3;
        int inc = sum;
#pragma unroll
        for (int d = 1; d < 32; d <<= 1) {
            int x = __shfl_up_sync(0xFFFFFFFFu, inc, d);
            if (t >= d) inc += x;
        }
        int exc = inc - sum;
        s_off[4 * t]     = exc;
        s_off[4 * t + 1] = exc + v0;
        s_off[4 * t + 2] = exc + v0 + v1;
        s_off[4 * t + 3] = exc + v0 + v1 + v2;
        if (t == 31) s_total = inc;
    }
    __syncthreads();

    if (t < WORDS) {
        int pos = s_off[t];
        uint32_t m = word;
        while (m) {
            int bit = __ffs(m) - 1;
            m &= m - 1;
            s_nbr[pos++] = (t * 32 + bit) * FC;   // premultiplied offset
        }
    }
    __syncthreads();

    const int n = s_total;
    const float inv = 1.0f / ((float)n + 1e-6f);
    const __half* __restrict__ xb = g_xt + (size_t)b * NN * FC + f8;

    float a0 = 0.f, a1 = 0.f, a2 = 0.f, a3 = 0.f;
    float a4 = 0.f, a5 = 0.f, a6 = 0.f, a7 = 0.f;

    // exact fp32 accumulate of one vector (tail)
#define ACC8(v)                                               \
    do { const __half2* _h = (const __half2*)&(v); float2 _p; \
        _p = __half22float2(_h[0]); a0 += _p.x; a1 += _p.y;   \
        _p = __half22float2(_h[1]); a2 += _p.x; a3 += _p.y;   \
        _p = __half22float2(_h[2]); a4 += _p.x; a5 += _p.y;   \
        _p = __half22float2(_h[3]); a6 += _p.x; a7 += _p.y; } while (0)
    // pair two neighbor vectors in fp16, then fp32-accumulate the pair sum
#define ACCPAIR(va, vb)                                           \
    do { const __half2* _ha = (const __half2*)&(va);              \
         const __half2* _hb = (const __half2*)&(vb); float2 _p;   \
        _p = __half22float2(__hadd2(_ha[0], _hb[0])); a0 += _p.x; a1 += _p.y; \
        _p = __half22float2(__hadd2(_ha[1], _hb[1])); a2 += _p.x; a3 += _p.y; \
        _p = __half22float2(__hadd2(_ha[2], _hb[2])); a4 += _p.x; a5 += _p.y; \
        _p = __half22float2(__hadd2(_ha[3], _hb[3])); a6 += _p.x; a7 += _p.y; } while (0)

    int k = 0;
    for (; k + 4 <= n; k += 4) {
        uint4 v0 = *(const uint4*)&xb[s_nbr[k]];
        uint4 v1 = *(const uint4*)&xb[s_nbr[k + 1]];
        uint4 v2 = *(const uint4*)&xb[s_nbr[k + 2]];
        uint4 v3 = *(const uint4*)&xb[s_nbr[k + 3]];
        ACCPAIR(v0, v1);
        ACCPAIR(v2, v3);
    }
    if (k + 2 <= n) {
        uint4 v0 = *(const uint4*)&xb[s_nbr[k]];
        uint4 v1 = *(const uint4*)&xb[s_nbr[k + 1]];
        ACCPAIR(v0, v1);
        k += 2;
    }
    if (k < n) {
        uint4 v0 = *(const uint4*)&xb[s_nbr[k]];
        ACC8(v0);
    }
#undef ACC8
#undef ACCPAIR

    float4 bl = *(const float4*)&bias[f8];
    float4 bh = *(const float4*)&bias[f8 + 4];
    float* o = out + ((size_t)b * NN + i) * FC + f8;
    *(float4*)o       = make_float4(a0 * inv + bl.x, a1 * inv + bl.y,
                                    a2 * inv + bl.z, a3 * inv + bl.w);
    *(float4*)(o + 4) = make_float4(a4 * inv + bh.x, a5 * inv + bh.y,
                                    a6 * inv + bh.z, a7 * inv + bh.w);
}

// =================== launch ===================
extern "C" void kernel_launch(void* const* d_in, const int* in_sizes, int n_in,
                              void* d_out, int out_size) {
    const float* x    = (const float*)d_in[0];
    const int*   ei   = (const int*)d_in[1];
    const float* w    = (const float*)d_in[2];
    const float* bias = (const float*)d_in[3];
    float*       out  = (float*)d_out;

    const int E = in_sizes[1] / 2;
    const int M = BB * NN;
    const int nb_sc = E / (256 * 4);          // 128 scatter blocks

    cudaFuncSetAttribute(k_gemm, cudaFuncAttributeMaxDynamicSharedMemorySize,
                         GEMM_SMEM);

    k_clear_adj<<<NN * WORDS / (256 * 8), 256>>>();
    k_front<<<NB_CVT + nb_sc + 64, 256>>>(x, ei, E, nb_sc, w);

    k_gemm<<<M / BM, 512, GEMM_SMEM>>>();

    k_aggregate<<<NN, 256>>>(bias, out);
}